// round 3
// baseline (speedup 1.0000x reference)
#include <cuda_runtime.h>
#include <cuda_bf16.h>
#include <cstdint>

// Problem constants
static constexpr int BB = 2;
static constexpr int LSEQ = 2048;
static constexpr int DM = 768;        // d_model
static constexpr int DI = 1536;       // d_inner
static constexpr int DS = 16;         // d_state
static constexpr int RK = 48;         // dt_rank
static constexpr int XD = RK + 2*DS;  // 80
static constexpr int MROWS = BB * LSEQ;  // 4096

// Scan chunking
static constexpr int NCH = 8;
static constexpr int CHUNK = LSEQ / NCH;   // 256
static constexpr int NCHAN = BB * DI;      // 3072

// Scratch (no cudaMalloc allowed)
__device__ float g_xp  [MROWS * DI];
__device__ float g_z   [MROWS * DI];
__device__ float g_xc  [MROWS * DI];
__device__ float g_xdbl[MROWS * XD];
__device__ float g_dt  [MROWS * DI];
__device__ float g_y   [MROWS * DI];
__device__ float g_P   [NCHAN * NCH * DS];
__device__ float g_H   [NCHAN * NCH * DS];
__device__ float g_Hin [NCHAN * NCH * DS];

__device__ __forceinline__ float siluf(float v) {
    return v / (1.f + __expf(-v));
}
__device__ __forceinline__ float softplusf(float v) {
    if (v > 20.f) return v;
    if (v < -20.f) return __expf(v);
    return log1pf(__expf(v));
}
__device__ __forceinline__ uint32_t f2tf32(float f) {
    uint32_t r;
    asm("cvt.rna.tf32.f32 %0, %1;" : "=r"(r) : "f"(f));
    return r;
}
__device__ __forceinline__ void mma_tf32(float c[4], uint32_t a0, uint32_t a1,
                                         uint32_t a2, uint32_t a3,
                                         uint32_t b0, uint32_t b1) {
    asm volatile(
        "mma.sync.aligned.m16n8k8.row.col.f32.tf32.tf32.f32 "
        "{%0,%1,%2,%3}, {%4,%5,%6,%7}, {%8,%9}, {%0,%1,%2,%3};"
        : "+f"(c[0]), "+f"(c[1]), "+f"(c[2]), "+f"(c[3])
        : "r"(a0), "r"(a1), "r"(a2), "r"(a3), "r"(b0), "r"(b1));
}

// ---------------------------------------------------------------------------
// tf32 tensor-core GEMM, double-buffered: C[M,N] = A[M,K] @ W[N,K]^T
// Block 128x128, k-tile 32, 8 warps (2M x 4N), warp tile 64x32.
// Dynamic smem: 2 x (As[128][36] + Ws[128][36]) of uint32 = 73728 B.
// EPI==0: plain store to C0 (ld = N)
// EPI==1: n < DI -> C0[m*DI+n], else C1[m*DI+n-DI]
// Requires M%128==0, N%128==0, K%32==0.
// ---------------------------------------------------------------------------
#define AS_(b,r,k) sm[(b)*4608 + (r)*36 + (k)]
#define WS_(b,r,k) sm[9216 + (b)*4608 + (r)*36 + (k)]

template<int EPI>
__global__ __launch_bounds__(256, 2)
void gemm_tf32(const float* __restrict__ A, const float* __restrict__ W,
               float* __restrict__ C0, float* __restrict__ C1,
               int M, int N, int K)
{
    extern __shared__ uint32_t sm[];

    const int tid  = threadIdx.x;
    const int lane = tid & 31;
    const int wid  = tid >> 5;
    const int wm   = wid & 1;          // 0..1  (M)
    const int wn   = wid >> 1;         // 0..3  (N)
    const int bm   = blockIdx.y * 128;
    const int bn   = blockIdx.x * 128;

    const int ldr = tid >> 3;          // 0..31
    const int ldc = (tid & 7) * 4;     // col*4
    const int g   = lane >> 2;
    const int q4  = lane & 3;

    float c[4][4][4];
#pragma unroll
    for (int i = 0; i < 4; ++i)
#pragma unroll
        for (int j = 0; j < 4; ++j)
#pragma unroll
            for (int q = 0; q < 4; ++q) c[i][j][q] = 0.f;

    const float* Abase = A + (size_t)bm * K + ldc;
    const float* Wbase = W + (size_t)bn * K + ldc;

    float4 av[4], wv[4];

#define LOADA(k0) {                                                         \
    _Pragma("unroll") for (int p = 0; p < 4; ++p)                           \
        av[p] = *(const float4*)(Abase + (size_t)(ldr + p*32) * K + (k0)); }
#define LOADW(k0) {                                                         \
    _Pragma("unroll") for (int p = 0; p < 4; ++p)                           \
        wv[p] = *(const float4*)(Wbase + (size_t)(ldr + p*32) * K + (k0)); }
#define STOREA(b) {                                                         \
    _Pragma("unroll") for (int p = 0; p < 4; ++p) {                         \
        int r = ldr + p*32;                                                 \
        AS_(b, r, ldc+0) = f2tf32(av[p].x); AS_(b, r, ldc+1) = f2tf32(av[p].y); \
        AS_(b, r, ldc+2) = f2tf32(av[p].z); AS_(b, r, ldc+3) = f2tf32(av[p].w); } }
#define STOREW(b) {                                                         \
    _Pragma("unroll") for (int p = 0; p < 4; ++p) {                         \
        int r = ldr + p*32;                                                 \
        WS_(b, r, ldc+0) = f2tf32(wv[p].x); WS_(b, r, ldc+1) = f2tf32(wv[p].y); \
        WS_(b, r, ldc+2) = f2tf32(wv[p].z); WS_(b, r, ldc+3) = f2tf32(wv[p].w); } }
#define COMPUTE(buf, ks) {                                                  \
    const int kk = (ks)*8 + q4;                                             \
    uint32_t a[4][4], b[4][2];                                              \
    _Pragma("unroll") for (int mt = 0; mt < 4; ++mt) {                      \
        int r = wm*64 + mt*16 + g;                                          \
        a[mt][0] = AS_(buf, r, kk);     a[mt][1] = AS_(buf, r+8, kk);       \
        a[mt][2] = AS_(buf, r, kk+4);   a[mt][3] = AS_(buf, r+8, kk+4); }   \
    _Pragma("unroll") for (int nt = 0; nt < 4; ++nt) {                      \
        int n = wn*32 + nt*8 + g;                                           \
        b[nt][0] = WS_(buf, n, kk);     b[nt][1] = WS_(buf, n, kk+4); }     \
    _Pragma("unroll") for (int mt = 0; mt < 4; ++mt)                        \
        _Pragma("unroll") for (int nt = 0; nt < 4; ++nt)                    \
            mma_tf32(c[mt][nt], a[mt][0], a[mt][1], a[mt][2], a[mt][3],    \
                     b[nt][0], b[nt][1]); }

    // prologue: fill buffer 0
    LOADA(0); LOADW(0);
    STOREA(0); STOREW(0);
    __syncthreads();

    const int NT = K / 32;
    for (int t = 0; t < NT; ++t) {
        const int cur = t & 1;
        const bool more = (t + 1 < NT);
        if (more) LOADA((t+1)*32);
        COMPUTE(cur, 0);
        COMPUTE(cur, 1);
        if (more) { STOREA(cur^1); LOADW((t+1)*32); }
        COMPUTE(cur, 2);
        COMPUTE(cur, 3);
        if (more) STOREW(cur^1);
        __syncthreads();
    }

    // epilogue
    const int q2 = (lane & 3) * 2;
    float* base;
    int ncol0, ldo;
    if (EPI == 0) { base = C0; ncol0 = bn; ldo = N; }
    else {
        base = (bn < DI) ? C0 : C1;
        ncol0 = (bn < DI) ? bn : (bn - DI);
        ldo = DI;
    }
#pragma unroll
    for (int mt = 0; mt < 4; ++mt) {
#pragma unroll
        for (int nt = 0; nt < 4; ++nt) {
            int row = bm + wm*64 + mt*16 + g;
            int col = ncol0 + wn*32 + nt*8 + q2;
            float2 v0 = make_float2(c[mt][nt][0], c[mt][nt][1]);
            float2 v1 = make_float2(c[mt][nt][2], c[mt][nt][3]);
            *(float2*)(base + (size_t)row * ldo + col) = v0;
            *(float2*)(base + (size_t)(row + 8) * ldo + col) = v1;
        }
    }
#undef LOADA
#undef LOADW
#undef STOREA
#undef STOREW
#undef COMPUTE
}

// ---------------------------------------------------------------------------
// Depthwise causal conv1d (K=4, left-pad 3) + bias + SiLU, float4 over d
// ---------------------------------------------------------------------------
__global__ __launch_bounds__(256)
void conv_silu_kernel(const float* __restrict__ xp, const float* __restrict__ cw,
                      const float* __restrict__ cb, float* __restrict__ xc)
{
    int idx = blockIdx.x * blockDim.x + threadIdx.x;   // over MROWS*DI/4
    if (idx >= MROWS * DI / 4) return;
    int dq = idx % (DI/4);
    int row = idx / (DI/4);
    int l = row % LSEQ;
    int d = dq * 4;

    // weights for 4 channels: cw[d..d+3][0..3] contiguous 16 floats
    float4 wq0 = *(const float4*)(cw + d*4 + 0);   // channel d:   taps 0..3
    float4 wq1 = *(const float4*)(cw + d*4 + 4);   // channel d+1
    float4 wq2 = *(const float4*)(cw + d*4 + 8);   // channel d+2
    float4 wq3 = *(const float4*)(cw + d*4 + 12);  // channel d+3

    float4 acc = *(const float4*)(cb + d);
    const float* p = xp + (size_t)row * DI + d;

    if (l >= 3) {
        float4 v = *(const float4*)(p - 3*DI);
        acc.x = fmaf(v.x, wq0.x, acc.x); acc.y = fmaf(v.y, wq1.x, acc.y);
        acc.z = fmaf(v.z, wq2.x, acc.z); acc.w = fmaf(v.w, wq3.x, acc.w);
    }
    if (l >= 2) {
        float4 v = *(const float4*)(p - 2*DI);
        acc.x = fmaf(v.x, wq0.y, acc.x); acc.y = fmaf(v.y, wq1.y, acc.y);
        acc.z = fmaf(v.z, wq2.y, acc.z); acc.w = fmaf(v.w, wq3.y, acc.w);
    }
    if (l >= 1) {
        float4 v = *(const float4*)(p - 1*DI);
        acc.x = fmaf(v.x, wq0.z, acc.x); acc.y = fmaf(v.y, wq1.z, acc.y);
        acc.z = fmaf(v.z, wq2.z, acc.z); acc.w = fmaf(v.w, wq3.z, acc.w);
    }
    {
        float4 v = *(const float4*)(p);
        acc.x = fmaf(v.x, wq0.w, acc.x); acc.y = fmaf(v.y, wq1.w, acc.y);
        acc.z = fmaf(v.z, wq2.w, acc.z); acc.w = fmaf(v.w, wq3.w, acc.w);
    }
    float4 r = make_float4(siluf(acc.x), siluf(acc.y), siluf(acc.z), siluf(acc.w));
    *(float4*)(xc + (size_t)row * DI + d) = r;
}

// ---------------------------------------------------------------------------
// Zero g_xdbl (for atomic K-split accumulation)
// ---------------------------------------------------------------------------
__global__ __launch_bounds__(256)
void zero_xdbl(float4* __restrict__ x)
{
    int i = blockIdx.x * 256 + threadIdx.x;    // MROWS*XD/4 = 81920
    x[i] = make_float4(0.f, 0.f, 0.f, 0.f);
}

// ---------------------------------------------------------------------------
// x_dbl = xc @ x_proj_w^T   [4096,1536] x [80,1536]^T -> [4096,80]
// 2-way K split (blockIdx.y), atomicAdd epilogue (2 addends -> deterministic).
// BM=32, 256 threads, 2x5 micro-tile. grid = (128, 2).
// ---------------------------------------------------------------------------
__global__ __launch_bounds__(256)
void gemm_xdbl(const float* __restrict__ A, const float* __restrict__ W,
               float* __restrict__ C)
{
    __shared__ float As[32][33];
    __shared__ float Ws[32][81];
    const int tid = threadIdx.x;
    const int bm = blockIdx.x * 32;
    const int kbeg = blockIdx.y * (DI/2);
    const int kend = kbeg + (DI/2);
    const int tr = tid >> 4;
    const int tc = tid & 15;
    const int cc = tid & 31;
    const int r0 = tid >> 5;

    float acc0[5] = {0,0,0,0,0};
    float acc1[5] = {0,0,0,0,0};

    for (int k0 = kbeg; k0 < kend; k0 += 32) {
        __syncthreads();
#pragma unroll
        for (int rr = r0; rr < 32; rr += 8)
            As[cc][rr] = A[(size_t)(bm + rr) * DI + k0 + cc];
#pragma unroll
        for (int n = r0; n < 80; n += 8)
            Ws[cc][n] = W[(size_t)n * DI + k0 + cc];
        __syncthreads();
#pragma unroll
        for (int k = 0; k < 32; ++k) {
            float a0 = As[k][tr*2];
            float a1 = As[k][tr*2+1];
#pragma unroll
            for (int j = 0; j < 5; ++j) {
                float w = Ws[k][tc*5 + j];
                acc0[j] = fmaf(a0, w, acc0[j]);
                acc1[j] = fmaf(a1, w, acc1[j]);
            }
        }
    }
#pragma unroll
    for (int j = 0; j < 5; ++j) {
        atomicAdd(&C[(size_t)(bm + tr*2    ) * XD + tc*5 + j], acc0[j]);
        atomicAdd(&C[(size_t)(bm + tr*2 + 1) * XD + tc*5 + j], acc1[j]);
    }
}

// ---------------------------------------------------------------------------
// dt = softplus( x_dbl[:, :48] @ dt_proj_w^T + b )  -> [4096,1536]
// Block: 64 rows x 128 cols, 256 threads, 8x4 micro-tile.
// s_in transposed [q][row] so inner loop is 3x LDS128 per 32 FFMA.
// grid = (12, 64)
// ---------------------------------------------------------------------------
__global__ __launch_bounds__(256)
void gemm_dt(const float* __restrict__ xdbl, const float* __restrict__ Wt,
             const float* __restrict__ bt, float* __restrict__ dt)
{
    __shared__ float s_inT[48][68];   // [q][row], pad 68 (16B-aligned rows)
    __shared__ float s_w[48][132];    // [q][col], pad 132
    const int tid = threadIdx.x;
    const int m0 = blockIdx.y * 64;
    const int n0 = blockIdx.x * 128;

    // load input tile transposed: read coalesced over q
    for (int i = tid; i < 64*48; i += 256) {
        int r = i / 48, q = i % 48;
        s_inT[q][r] = xdbl[(size_t)(m0 + r) * XD + q];
    }
    // load weights: read coalesced over q, store [q][col]
    for (int i = tid; i < 128*48; i += 256) {
        int col = i / 48, q = i % 48;
        s_w[q][col] = Wt[(size_t)(n0 + col) * RK + q];
    }
    __syncthreads();

    const int col = (tid & 31) * 4;
    const int row0 = (tid >> 5) * 8;

    float acc[8][4];
    {
        float4 b4 = *(const float4*)(bt + n0 + col);
#pragma unroll
        for (int r = 0; r < 8; ++r) {
            acc[r][0] = b4.x; acc[r][1] = b4.y; acc[r][2] = b4.z; acc[r][3] = b4.w;
        }
    }
#pragma unroll
    for (int q = 0; q < 48; ++q) {
        float4 a0 = *(const float4*)&s_inT[q][row0];
        float4 a1 = *(const float4*)&s_inT[q][row0 + 4];
        float4 w4 = *(const float4*)&s_w[q][col];
        float a[8] = {a0.x,a0.y,a0.z,a0.w,a1.x,a1.y,a1.z,a1.w};
#pragma unroll
        for (int r = 0; r < 8; ++r) {
            acc[r][0] = fmaf(a[r], w4.x, acc[r][0]);
            acc[r][1] = fmaf(a[r], w4.y, acc[r][1]);
            acc[r][2] = fmaf(a[r], w4.z, acc[r][2]);
            acc[r][3] = fmaf(a[r], w4.w, acc[r][3]);
        }
    }
#pragma unroll
    for (int r = 0; r < 8; ++r) {
        float* p = dt + (size_t)(m0 + row0 + r) * DI + n0 + col;
        float4 v = make_float4(softplusf(acc[r][0]), softplusf(acc[r][1]),
                               softplusf(acc[r][2]), softplusf(acc[r][3]));
        *(float4*)p = v;
    }
}

// ---------------------------------------------------------------------------
// Chunked selective scan, pass 1: per (channel, chunk) compute
//   P = prod_l a_l  and  H = local scan final state (h0 = 0)
// ---------------------------------------------------------------------------
__global__ __launch_bounds__(128)
void scan_pass1(const float* __restrict__ xdbl, const float* __restrict__ dt,
                const float* __restrict__ xc, const float* __restrict__ A_log,
                float* __restrict__ P, float* __restrict__ H)
{
    const int s = threadIdx.x & 15;
    const int unit = blockIdx.x * 8 + (threadIdx.x >> 4);
    const int ch = unit >> 3;          // 0..3071
    const int c  = unit & 7;           // chunk
    const int b = ch / DI;
    const int d = ch % DI;

    const float A = -__expf(A_log[d*DS + s]);
    float h = 0.f, Pv = 1.f;

    const int row0 = b * LSEQ + c * CHUNK;
    const float* dt_p = dt + (size_t)row0 * DI + d;
    const float* xc_p = xc + (size_t)row0 * DI + d;
    const float* xd_p = xdbl + (size_t)row0 * XD;

#pragma unroll 4
    for (int l = 0; l < CHUNK; ++l) {
        float dtv = __ldg(dt_p);
        float xcv = __ldg(xc_p);
        float Bv  = __ldg(xd_p + RK + s);
        float a = __expf(dtv * A);
        Pv *= a;
        h = fmaf(a, h, dtv * xcv * Bv);
        dt_p += DI; xc_p += DI; xd_p += XD;
    }
    P[unit * DS + s] = Pv;
    H[unit * DS + s] = h;
}

// ---------------------------------------------------------------------------
// Combine: serial scan over the 8 chunk transitions per (channel, state).
// ---------------------------------------------------------------------------
__global__ __launch_bounds__(256)
void scan_combine(const float* __restrict__ P, const float* __restrict__ H,
                  float* __restrict__ Hin)
{
    int idx = blockIdx.x * blockDim.x + threadIdx.x;
    if (idx >= NCHAN * DS) return;
    int ch = idx >> 4;
    int s = idx & 15;
    float run = 0.f;
#pragma unroll
    for (int c = 0; c < NCH; ++c) {
        int o = (ch * NCH + c) * DS + s;
        Hin[o] = run;
        run = fmaf(P[o], run, H[o]);
    }
}

// ---------------------------------------------------------------------------
// Pass 2: replay each chunk from its correct incoming state, emit
//   y = (sum_s h*C + xc*D) * silu(z)
// ---------------------------------------------------------------------------
__global__ __launch_bounds__(128)
void scan_pass2(const float* __restrict__ xdbl, const float* __restrict__ dt,
                const float* __restrict__ xc, const float* __restrict__ z,
                const float* __restrict__ A_log, const float* __restrict__ Dp,
                const float* __restrict__ Hin, float* __restrict__ y)
{
    const int s = threadIdx.x & 15;
    const int unit = blockIdx.x * 8 + (threadIdx.x >> 4);
    const int ch = unit >> 3;
    const int c  = unit & 7;
    const int b = ch / DI;
    const int d = ch % DI;

    const float A = -__expf(A_log[d*DS + s]);
    const float Dv = Dp[d];
    float h = Hin[unit * DS + s];

    const int row0 = b * LSEQ + c * CHUNK;
    const float* dt_p = dt + (size_t)row0 * DI + d;
    const float* xc_p = xc + (size_t)row0 * DI + d;
    const float* z_p  = z  + (size_t)row0 * DI + d;
    const float* xd_p = xdbl + (size_t)row0 * XD;
    float* y_p = y + (size_t)row0 * DI + d;

#pragma unroll 4
    for (int l = 0; l < CHUNK; ++l) {
        float dtv = __ldg(dt_p);
        float xcv = __ldg(xc_p);
        float Bv  = __ldg(xd_p + RK + s);
        float Cv  = __ldg(xd_p + RK + DS + s);

        float a = __expf(dtv * A);
        h = fmaf(a, h, dtv * xcv * Bv);
        float p = h * Cv;
        p += __shfl_xor_sync(0xffffffffu, p, 1);
        p += __shfl_xor_sync(0xffffffffu, p, 2);
        p += __shfl_xor_sync(0xffffffffu, p, 4);
        p += __shfl_xor_sync(0xffffffffu, p, 8);
        if (s == 0) {
            float zv = __ldg(z_p);
            *y_p = (p + xcv * Dv) * siluf(zv);
        }
        dt_p += DI; xc_p += DI; z_p += DI; y_p += DI; xd_p += XD;
    }
}

// ---------------------------------------------------------------------------
extern "C" void kernel_launch(void* const* d_in, const int* in_sizes, int n_in,
                              void* d_out, int out_size)
{
    const float* x          = (const float*)d_in[0];
    const float* in_proj_w  = (const float*)d_in[1];
    const float* conv_w     = (const float*)d_in[2];
    const float* conv_b     = (const float*)d_in[3];
    const float* A_log      = (const float*)d_in[4];
    const float* D_param    = (const float*)d_in[5];
    const float* x_proj_w   = (const float*)d_in[6];
    const float* dt_proj_w  = (const float*)d_in[7];
    const float* dt_proj_b  = (const float*)d_in[8];
    const float* out_proj_w = (const float*)d_in[9];
    float* out = (float*)d_out;

    float *xp, *zb, *xc, *xdbl, *dtb, *yb, *Pb, *Hb, *Hinb;
    cudaGetSymbolAddress((void**)&xp,   g_xp);
    cudaGetSymbolAddress((void**)&zb,   g_z);
    cudaGetSymbolAddress((void**)&xc,   g_xc);
    cudaGetSymbolAddress((void**)&xdbl, g_xdbl);
    cudaGetSymbolAddress((void**)&dtb,  g_dt);
    cudaGetSymbolAddress((void**)&yb,   g_y);
    cudaGetSymbolAddress((void**)&Pb,   g_P);
    cudaGetSymbolAddress((void**)&Hb,   g_H);
    cudaGetSymbolAddress((void**)&Hinb, g_Hin);

    const int GEMM_SMEM = 2 * 2 * 128 * 36 * 4;   // 73728 B
    cudaFuncSetAttribute(gemm_tf32<0>, cudaFuncAttributeMaxDynamicSharedMemorySize, GEMM_SMEM);
    cudaFuncSetAttribute(gemm_tf32<1>, cudaFuncAttributeMaxDynamicSharedMemorySize, GEMM_SMEM);

    // 0. zero x_dbl accumulator (atomic K-split target)
    zero_xdbl<<<(MROWS*XD/4)/256, 256>>>((float4*)xdbl);
    // 1. xz = x @ in_proj_w^T, split -> xp, z   (tf32 tensor cores)
    {
        dim3 grid(2*DI/128, MROWS/128);
        gemm_tf32<1><<<grid, 256, GEMM_SMEM>>>(x, in_proj_w, xp, zb, MROWS, 2*DI, DM);
    }
    // 2. causal depthwise conv + bias + SiLU -> xc
    {
        int total = MROWS * DI / 4;
        conv_silu_kernel<<<(total + 255)/256, 256>>>(xp, conv_w, conv_b, xc);
    }
    // 3. x_dbl = xc @ x_proj_w^T  (2-way K split, atomic accumulate)
    {
        dim3 grid(MROWS/32, 2);
        gemm_xdbl<<<grid, 256>>>(xc, x_proj_w, xdbl);
    }
    // 4. dt = softplus(dt_low @ dt_proj_w^T + b)
    {
        dim3 grid(DI/128, MROWS/64);
        gemm_dt<<<grid, 256>>>(xdbl, dt_proj_w, dt_proj_b, dtb);
    }
    // 5. chunked selective scan
    scan_pass1<<<(NCHAN*NCH)/8, 128>>>(xdbl, dtb, xc, A_log, Pb, Hb);
    scan_combine<<<(NCHAN*DS + 255)/256, 256>>>(Pb, Hb, Hinb);
    scan_pass2<<<(NCHAN*NCH)/8, 128>>>(xdbl, dtb, xc, zb, A_log, D_param, Hinb, yb);
    // 6. out = y @ out_proj_w^T   (tf32 tensor cores)
    {
        dim3 grid(DM/128, MROWS/128);
        gemm_tf32<0><<<grid, 256, GEMM_SMEM>>>(yb, out_proj_w, out, nullptr, MROWS, DM, DI);
    }
}

// round 4
// speedup vs baseline: 1.4620x; 1.4620x over previous
#include <cuda_runtime.h>
#include <cuda_bf16.h>
#include <cstdint>

// Problem constants
static constexpr int BB = 2;
static constexpr int LSEQ = 2048;
static constexpr int DM = 768;        // d_model
static constexpr int DI = 1536;       // d_inner
static constexpr int DS = 16;         // d_state
static constexpr int RK = 48;         // dt_rank
static constexpr int XD = RK + 2*DS;  // 80
static constexpr int MROWS = BB * LSEQ;  // 4096

// Scan chunking
static constexpr int NCH = 8;
static constexpr int CHUNK = LSEQ / NCH;   // 256
static constexpr int NCHAN = BB * DI;      // 3072

// Scratch (no cudaMalloc allowed)
__device__ float g_xp  [MROWS * DI];
__device__ float g_z   [MROWS * DI];
__device__ float g_xc  [MROWS * DI];
__device__ float g_xdbl[MROWS * XD];
__device__ float g_dt  [MROWS * DI];
__device__ float g_y   [MROWS * DI];
__device__ float g_P   [NCHAN * NCH * DS];
__device__ float g_H   [NCHAN * NCH * DS];
__device__ float g_Hin [NCHAN * NCH * DS];

__device__ __forceinline__ float siluf(float v) {
    return v / (1.f + __expf(-v));
}
__device__ __forceinline__ float softplusf(float v) {
    if (v > 20.f) return v;
    if (v < -20.f) return __expf(v);
    return log1pf(__expf(v));
}
__device__ __forceinline__ uint32_t f2tf32(float f) {
    uint32_t r;
    asm("cvt.rna.tf32.f32 %0, %1;" : "=r"(r) : "f"(f));
    return r;
}
__device__ __forceinline__ void mma_tf32(float c[4], uint32_t a0, uint32_t a1,
                                         uint32_t a2, uint32_t a3,
                                         uint32_t b0, uint32_t b1) {
    asm volatile(
        "mma.sync.aligned.m16n8k8.row.col.f32.tf32.tf32.f32 "
        "{%0,%1,%2,%3}, {%4,%5,%6,%7}, {%8,%9}, {%0,%1,%2,%3};"
        : "+f"(c[0]), "+f"(c[1]), "+f"(c[2]), "+f"(c[3])
        : "r"(a0), "r"(a1), "r"(a2), "r"(a3), "r"(b0), "r"(b1));
}
__device__ __forceinline__ void cp16(uint32_t saddr, const float* g) {
    asm volatile("cp.async.cg.shared.global [%0], [%1], 16;" :: "r"(saddr), "l"(g));
}
#define CP_COMMIT() asm volatile("cp.async.commit_group;")
#define CP_WAIT(n)  asm volatile("cp.async.wait_group %0;" :: "n"(n))

// ---------------------------------------------------------------------------
// tf32 tensor-core GEMM, cp.async 2-stage pipeline: C[M,N] = A[M,K] @ W[N,K]^T
// Block 128x128, k-tile 32, 8 warps (2M x 4N), warp tile 64x32.
// Dynamic smem (float): 2 x (As[128][36] + Ws[128][36]) = 73728 B.
// Conversion to tf32 happens AFTER the smem load (fragment path).
// EPI==0: plain store to C0 (ld = N); EPI==1: split at DI -> C0 / C1.
// Requires M%128==0, N%128==0, K%32==0.
// ---------------------------------------------------------------------------
#define ASf(b,r,k) smf[(b)*4608 + (r)*36 + (k)]
#define WSf(b,r,k) smf[9216 + (b)*4608 + (r)*36 + (k)]

template<int EPI>
__global__ __launch_bounds__(256, 2)
void gemm_tf32(const float* __restrict__ A, const float* __restrict__ W,
               float* __restrict__ C0, float* __restrict__ C1,
               int M, int N, int K)
{
    extern __shared__ float smf[];
    uint32_t sbase;
    {
        uint64_t tmp = __cvta_generic_to_shared(smf);
        sbase = (uint32_t)tmp;
    }

    const int tid  = threadIdx.x;
    const int lane = tid & 31;
    const int wid  = tid >> 5;
    const int wm   = wid & 1;          // 0..1  (M)
    const int wn   = wid >> 1;         // 0..3  (N)
    const int bm   = blockIdx.y * 128;
    const int bn   = blockIdx.x * 128;

    const int ldr = tid >> 3;          // 0..31
    const int ldc = (tid & 7) * 4;     // col*4
    const int g   = lane >> 2;
    const int q4  = lane & 3;

    float c[4][4][4];
#pragma unroll
    for (int i = 0; i < 4; ++i)
#pragma unroll
        for (int j = 0; j < 4; ++j)
#pragma unroll
            for (int q = 0; q < 4; ++q) c[i][j][q] = 0.f;

    const float* Abase = A + (size_t)bm * K + ldc;
    const float* Wbase = W + (size_t)bn * K + ldc;

#define ISSUE(k0, buf) {                                                     \
    _Pragma("unroll") for (int p = 0; p < 4; ++p) {                          \
        int r = ldr + p*32;                                                  \
        cp16(sbase + (uint32_t)(((buf)*4608 + r*36 + ldc))*4,                \
             Abase + (size_t)r * K + (k0));                                  \
        cp16(sbase + (uint32_t)((9216 + (buf)*4608 + r*36 + ldc))*4,         \
             Wbase + (size_t)r * K + (k0)); } }

#define COMPUTE(buf, ks) {                                                   \
    const int kk = (ks)*8 + q4;                                              \
    uint32_t a[4][4], b[4][2];                                               \
    _Pragma("unroll") for (int mt = 0; mt < 4; ++mt) {                       \
        int r = wm*64 + mt*16 + g;                                           \
        a[mt][0] = f2tf32(ASf(buf, r, kk));                                  \
        a[mt][1] = f2tf32(ASf(buf, r+8, kk));                                \
        a[mt][2] = f2tf32(ASf(buf, r, kk+4));                                \
        a[mt][3] = f2tf32(ASf(buf, r+8, kk+4)); }                            \
    _Pragma("unroll") for (int nt = 0; nt < 4; ++nt) {                       \
        int n = wn*32 + nt*8 + g;                                            \
        b[nt][0] = f2tf32(WSf(buf, n, kk));                                  \
        b[nt][1] = f2tf32(WSf(buf, n, kk+4)); }                              \
    _Pragma("unroll") for (int mt = 0; mt < 4; ++mt)                         \
        _Pragma("unroll") for (int nt = 0; nt < 4; ++nt)                     \
            mma_tf32(c[mt][nt], a[mt][0], a[mt][1], a[mt][2], a[mt][3],     \
                     b[nt][0], b[nt][1]); }

    ISSUE(0, 0);
    CP_COMMIT();

    const int NT = K / 32;
    for (int t = 0; t < NT; ++t) {
        const int cur = t & 1;
        if (t + 1 < NT) {
            ISSUE((t+1)*32, cur^1);
            CP_COMMIT();
            CP_WAIT(1);
        } else {
            CP_WAIT(0);
        }
        __syncthreads();
        COMPUTE(cur, 0);
        COMPUTE(cur, 1);
        COMPUTE(cur, 2);
        COMPUTE(cur, 3);
        __syncthreads();
    }

    // epilogue
    const int q2 = (lane & 3) * 2;
    float* base;
    int ncol0, ldo;
    if (EPI == 0) { base = C0; ncol0 = bn; ldo = N; }
    else {
        base = (bn < DI) ? C0 : C1;
        ncol0 = (bn < DI) ? bn : (bn - DI);
        ldo = DI;
    }
#pragma unroll
    for (int mt = 0; mt < 4; ++mt) {
#pragma unroll
        for (int nt = 0; nt < 4; ++nt) {
            int row = bm + wm*64 + mt*16 + g;
            int col = ncol0 + wn*32 + nt*8 + q2;
            float2 v0 = make_float2(c[mt][nt][0], c[mt][nt][1]);
            float2 v1 = make_float2(c[mt][nt][2], c[mt][nt][3]);
            *(float2*)(base + (size_t)row * ldo + col) = v0;
            *(float2*)(base + (size_t)(row + 8) * ldo + col) = v1;
        }
    }
#undef ISSUE
#undef COMPUTE
}

// ---------------------------------------------------------------------------
// Depthwise causal conv1d (K=4, left-pad 3) + bias + SiLU, float4 over d
// ---------------------------------------------------------------------------
__global__ __launch_bounds__(256)
void conv_silu_kernel(const float* __restrict__ xp, const float* __restrict__ cw,
                      const float* __restrict__ cb, float* __restrict__ xc)
{
    int idx = blockIdx.x * blockDim.x + threadIdx.x;   // over MROWS*DI/4
    if (idx >= MROWS * DI / 4) return;
    int dq = idx % (DI/4);
    int row = idx / (DI/4);
    int l = row % LSEQ;
    int d = dq * 4;

    float4 wq0 = *(const float4*)(cw + d*4 + 0);
    float4 wq1 = *(const float4*)(cw + d*4 + 4);
    float4 wq2 = *(const float4*)(cw + d*4 + 8);
    float4 wq3 = *(const float4*)(cw + d*4 + 12);

    float4 acc = *(const float4*)(cb + d);
    const float* p = xp + (size_t)row * DI + d;

    if (l >= 3) {
        float4 v = *(const float4*)(p - 3*DI);
        acc.x = fmaf(v.x, wq0.x, acc.x); acc.y = fmaf(v.y, wq1.x, acc.y);
        acc.z = fmaf(v.z, wq2.x, acc.z); acc.w = fmaf(v.w, wq3.x, acc.w);
    }
    if (l >= 2) {
        float4 v = *(const float4*)(p - 2*DI);
        acc.x = fmaf(v.x, wq0.y, acc.x); acc.y = fmaf(v.y, wq1.y, acc.y);
        acc.z = fmaf(v.z, wq2.y, acc.z); acc.w = fmaf(v.w, wq3.y, acc.w);
    }
    if (l >= 1) {
        float4 v = *(const float4*)(p - 1*DI);
        acc.x = fmaf(v.x, wq0.z, acc.x); acc.y = fmaf(v.y, wq1.z, acc.y);
        acc.z = fmaf(v.z, wq2.z, acc.z); acc.w = fmaf(v.w, wq3.z, acc.w);
    }
    {
        float4 v = *(const float4*)(p);
        acc.x = fmaf(v.x, wq0.w, acc.x); acc.y = fmaf(v.y, wq1.w, acc.y);
        acc.z = fmaf(v.z, wq2.w, acc.z); acc.w = fmaf(v.w, wq3.w, acc.w);
    }
    float4 r = make_float4(siluf(acc.x), siluf(acc.y), siluf(acc.z), siluf(acc.w));
    *(float4*)(xc + (size_t)row * DI + d) = r;
}

// ---------------------------------------------------------------------------
// Zero g_xdbl (for atomic K-split accumulation)
// ---------------------------------------------------------------------------
__global__ __launch_bounds__(256)
void zero_xdbl(float4* __restrict__ x)
{
    int i = blockIdx.x * 256 + threadIdx.x;    // MROWS*XD/4 = 81920
    x[i] = make_float4(0.f, 0.f, 0.f, 0.f);
}

// ---------------------------------------------------------------------------
// x_dbl = xc @ x_proj_w^T   [4096,1536] x [80,1536]^T -> [4096,80]
// Double-buffered, 2-way K split, atomicAdd epilogue (2 addends onto zero ->
// deterministic). BM=32, 256 threads, 2x5 micro-tile. grid = (128, 2).
// ---------------------------------------------------------------------------
__global__ __launch_bounds__(256)
void gemm_xdbl(const float* __restrict__ A, const float* __restrict__ W,
               float* __restrict__ C)
{
    __shared__ float As[2][32][33];
    __shared__ float Ws[2][32][81];
    const int tid = threadIdx.x;
    const int bm = blockIdx.x * 32;
    const int kbeg = blockIdx.y * (DI/2);
    const int tr = tid >> 4;
    const int tc = tid & 15;
    const int cc = tid & 31;
    const int r0 = tid >> 5;

    float acc0[5] = {0,0,0,0,0};
    float acc1[5] = {0,0,0,0,0};
    float a_st[4], w_st[10];

#define XLOAD(k0) {                                                          \
    _Pragma("unroll") for (int p = 0; p < 4; ++p)                            \
        a_st[p] = A[(size_t)(bm + r0 + p*8) * DI + (k0) + cc];               \
    _Pragma("unroll") for (int p = 0; p < 10; ++p)                           \
        w_st[p] = W[(size_t)(r0 + p*8) * DI + (k0) + cc]; }
#define XSTORE(buf) {                                                        \
    _Pragma("unroll") for (int p = 0; p < 4; ++p)                            \
        As[buf][cc][r0 + p*8] = a_st[p];                                     \
    _Pragma("unroll") for (int p = 0; p < 10; ++p)                           \
        Ws[buf][cc][r0 + p*8] = w_st[p]; }

    XLOAD(kbeg);
    XSTORE(0);
    __syncthreads();

    const int NT = (DI/2) / 32;   // 24
    for (int t = 0; t < NT; ++t) {
        const int cur = t & 1;
        if (t + 1 < NT) XLOAD(kbeg + (t+1)*32);
#pragma unroll
        for (int k = 0; k < 32; ++k) {
            float a0 = As[cur][k][tr*2];
            float a1 = As[cur][k][tr*2+1];
#pragma unroll
            for (int j = 0; j < 5; ++j) {
                float w = Ws[cur][k][tc*5 + j];
                acc0[j] = fmaf(a0, w, acc0[j]);
                acc1[j] = fmaf(a1, w, acc1[j]);
            }
        }
        if (t + 1 < NT) {
            XSTORE(cur^1);
            __syncthreads();
        }
    }
#pragma unroll
    for (int j = 0; j < 5; ++j) {
        atomicAdd(&C[(size_t)(bm + tr*2    ) * XD + tc*5 + j], acc0[j]);
        atomicAdd(&C[(size_t)(bm + tr*2 + 1) * XD + tc*5 + j], acc1[j]);
    }
#undef XLOAD
#undef XSTORE
}

// ---------------------------------------------------------------------------
// dt = softplus( x_dbl[:, :48] @ dt_proj_w^T + b )  -> [4096,1536]
// Block: 64 rows x 128 cols, 256 threads, 8x4 micro-tile. grid = (12, 64)
// ---------------------------------------------------------------------------
__global__ __launch_bounds__(256)
void gemm_dt(const float* __restrict__ xdbl, const float* __restrict__ Wt,
             const float* __restrict__ bt, float* __restrict__ dt)
{
    __shared__ float s_inT[48][68];   // [q][row]
    __shared__ float s_w[48][132];    // [q][col]
    const int tid = threadIdx.x;
    const int m0 = blockIdx.y * 64;
    const int n0 = blockIdx.x * 128;

    for (int i = tid; i < 64*48; i += 256) {
        int r = i / 48, q = i % 48;
        s_inT[q][r] = xdbl[(size_t)(m0 + r) * XD + q];
    }
    for (int i = tid; i < 128*48; i += 256) {
        int col = i / 48, q = i % 48;
        s_w[q][col] = Wt[(size_t)(n0 + col) * RK + q];
    }
    __syncthreads();

    const int col = (tid & 31) * 4;
    const int row0 = (tid >> 5) * 8;

    float acc[8][4];
    {
        float4 b4 = *(const float4*)(bt + n0 + col);
#pragma unroll
        for (int r = 0; r < 8; ++r) {
            acc[r][0] = b4.x; acc[r][1] = b4.y; acc[r][2] = b4.z; acc[r][3] = b4.w;
        }
    }
#pragma unroll
    for (int q = 0; q < 48; ++q) {
        float4 a0 = *(const float4*)&s_inT[q][row0];
        float4 a1 = *(const float4*)&s_inT[q][row0 + 4];
        float4 w4 = *(const float4*)&s_w[q][col];
        float a[8] = {a0.x,a0.y,a0.z,a0.w,a1.x,a1.y,a1.z,a1.w};
#pragma unroll
        for (int r = 0; r < 8; ++r) {
            acc[r][0] = fmaf(a[r], w4.x, acc[r][0]);
            acc[r][1] = fmaf(a[r], w4.y, acc[r][1]);
            acc[r][2] = fmaf(a[r], w4.z, acc[r][2]);
            acc[r][3] = fmaf(a[r], w4.w, acc[r][3]);
        }
    }
#pragma unroll
    for (int r = 0; r < 8; ++r) {
        float* p = dt + (size_t)(m0 + row0 + r) * DI + n0 + col;
        float4 v = make_float4(softplusf(acc[r][0]), softplusf(acc[r][1]),
                               softplusf(acc[r][2]), softplusf(acc[r][3]));
        *(float4*)p = v;
    }
}

// ---------------------------------------------------------------------------
// Chunked selective scan, pass 1. 8 lanes per (channel, chunk) unit, lane
// handles states {2s, 2s+1} with float2 B loads.
// P = prod_l a_l, H = local final state (h0 = 0).
// 256 threads = 32 units/block; grid = 24576/32 = 768.
// ---------------------------------------------------------------------------
__global__ __launch_bounds__(256)
void scan_pass1(const float* __restrict__ xdbl, const float* __restrict__ dt,
                const float* __restrict__ xc, const float* __restrict__ A_log,
                float* __restrict__ P, float* __restrict__ H)
{
    const int s = threadIdx.x & 7;
    const int unit = blockIdx.x * 32 + (threadIdx.x >> 3);
    const int ch = unit >> 3;          // 0..3071
    const int c  = unit & 7;           // chunk
    const int b = ch / DI;
    const int d = ch % DI;

    float2 Alog2 = *(const float2*)(A_log + d*DS + 2*s);
    const float A0 = -__expf(Alog2.x);
    const float A1 = -__expf(Alog2.y);
    float h0 = 0.f, h1 = 0.f, P0 = 1.f, P1 = 1.f;

    const int row0 = b * LSEQ + c * CHUNK;
    const float* dt_p = dt + (size_t)row0 * DI + d;
    const float* xc_p = xc + (size_t)row0 * DI + d;
    const float* xd_p = xdbl + (size_t)row0 * XD;

#pragma unroll 4
    for (int l = 0; l < CHUNK; ++l) {
        float dtv = __ldg(dt_p);
        float xcv = __ldg(xc_p);
        float2 Bv = *(const float2*)(xd_p + RK + 2*s);
        float a0 = __expf(dtv * A0);
        float a1 = __expf(dtv * A1);
        float bx = dtv * xcv;
        P0 *= a0; P1 *= a1;
        h0 = fmaf(a0, h0, bx * Bv.x);
        h1 = fmaf(a1, h1, bx * Bv.y);
        dt_p += DI; xc_p += DI; xd_p += XD;
    }
    *(float2*)(P + unit * DS + 2*s) = make_float2(P0, P1);
    *(float2*)(H + unit * DS + 2*s) = make_float2(h0, h1);
}

// ---------------------------------------------------------------------------
// Combine: serial scan over the 8 chunk transitions per (channel, state).
// ---------------------------------------------------------------------------
__global__ __launch_bounds__(256)
void scan_combine(const float* __restrict__ P, const float* __restrict__ H,
                  float* __restrict__ Hin)
{
    int idx = blockIdx.x * blockDim.x + threadIdx.x;
    if (idx >= NCHAN * DS) return;
    int ch = idx >> 4;
    int s = idx & 15;
    float run = 0.f;
#pragma unroll
    for (int c = 0; c < NCH; ++c) {
        int o = (ch * NCH + c) * DS + s;
        Hin[o] = run;
        run = fmaf(P[o], run, H[o]);
    }
}

// ---------------------------------------------------------------------------
// Pass 2: replay each chunk from its correct incoming state, emit
//   y = (sum_s h*C + xc*D) * silu(z).  8 lanes/unit, 2 states/lane.
// ---------------------------------------------------------------------------
__global__ __launch_bounds__(256)
void scan_pass2(const float* __restrict__ xdbl, const float* __restrict__ dt,
                const float* __restrict__ xc, const float* __restrict__ z,
                const float* __restrict__ A_log, const float* __restrict__ Dp,
                const float* __restrict__ Hin, float* __restrict__ y)
{
    const int s = threadIdx.x & 7;
    const int unit = blockIdx.x * 32 + (threadIdx.x >> 3);
    const int ch = unit >> 3;
    const int c  = unit & 7;
    const int b = ch / DI;
    const int d = ch % DI;

    float2 Alog2 = *(const float2*)(A_log + d*DS + 2*s);
    const float A0 = -__expf(Alog2.x);
    const float A1 = -__expf(Alog2.y);
    const float Dv = Dp[d];
    float2 h2 = *(const float2*)(Hin + unit * DS + 2*s);
    float h0 = h2.x, h1 = h2.y;

    const int row0 = b * LSEQ + c * CHUNK;
    const float* dt_p = dt + (size_t)row0 * DI + d;
    const float* xc_p = xc + (size_t)row0 * DI + d;
    const float* z_p  = z  + (size_t)row0 * DI + d;
    const float* xd_p = xdbl + (size_t)row0 * XD;
    float* y_p = y + (size_t)row0 * DI + d;

#pragma unroll 4
    for (int l = 0; l < CHUNK; ++l) {
        float dtv = __ldg(dt_p);
        float xcv = __ldg(xc_p);
        float2 Bv = *(const float2*)(xd_p + RK + 2*s);
        float2 Cv = *(const float2*)(xd_p + RK + DS + 2*s);

        float a0 = __expf(dtv * A0);
        float a1 = __expf(dtv * A1);
        float bx = dtv * xcv;
        h0 = fmaf(a0, h0, bx * Bv.x);
        h1 = fmaf(a1, h1, bx * Bv.y);
        float p = fmaf(h0, Cv.x, h1 * Cv.y);
        p += __shfl_xor_sync(0xffffffffu, p, 1);
        p += __shfl_xor_sync(0xffffffffu, p, 2);
        p += __shfl_xor_sync(0xffffffffu, p, 4);
        if (s == 0) {
            float zv = __ldg(z_p);
            *y_p = (p + xcv * Dv) * siluf(zv);
        }
        dt_p += DI; xc_p += DI; z_p += DI; y_p += DI; xd_p += XD;
    }
}

// ---------------------------------------------------------------------------
extern "C" void kernel_launch(void* const* d_in, const int* in_sizes, int n_in,
                              void* d_out, int out_size)
{
    const float* x          = (const float*)d_in[0];
    const float* in_proj_w  = (const float*)d_in[1];
    const float* conv_w     = (const float*)d_in[2];
    const float* conv_b     = (const float*)d_in[3];
    const float* A_log      = (const float*)d_in[4];
    const float* D_param    = (const float*)d_in[5];
    const float* x_proj_w   = (const float*)d_in[6];
    const float* dt_proj_w  = (const float*)d_in[7];
    const float* dt_proj_b  = (const float*)d_in[8];
    const float* out_proj_w = (const float*)d_in[9];
    float* out = (float*)d_out;

    float *xp, *zb, *xc, *xdbl, *dtb, *yb, *Pb, *Hb, *Hinb;
    cudaGetSymbolAddress((void**)&xp,   g_xp);
    cudaGetSymbolAddress((void**)&zb,   g_z);
    cudaGetSymbolAddress((void**)&xc,   g_xc);
    cudaGetSymbolAddress((void**)&xdbl, g_xdbl);
    cudaGetSymbolAddress((void**)&dtb,  g_dt);
    cudaGetSymbolAddress((void**)&yb,   g_y);
    cudaGetSymbolAddress((void**)&Pb,   g_P);
    cudaGetSymbolAddress((void**)&Hb,   g_H);
    cudaGetSymbolAddress((void**)&Hinb, g_Hin);

    const int GEMM_SMEM = 2 * 2 * 128 * 36 * 4;   // 73728 B
    cudaFuncSetAttribute(gemm_tf32<0>, cudaFuncAttributeMaxDynamicSharedMemorySize, GEMM_SMEM);
    cudaFuncSetAttribute(gemm_tf32<1>, cudaFuncAttributeMaxDynamicSharedMemorySize, GEMM_SMEM);

    // 0. zero x_dbl accumulator (atomic K-split target)
    zero_xdbl<<<(MROWS*XD/4)/256, 256>>>((float4*)xdbl);
    // 1. xz = x @ in_proj_w^T, split -> xp, z   (tf32 tensor cores, cp.async)
    {
        dim3 grid(2*DI/128, MROWS/128);
        gemm_tf32<1><<<grid, 256, GEMM_SMEM>>>(x, in_proj_w, xp, zb, MROWS, 2*DI, DM);
    }
    // 2. causal depthwise conv + bias + SiLU -> xc
    {
        int total = MROWS * DI / 4;
        conv_silu_kernel<<<(total + 255)/256, 256>>>(xp, conv_w, conv_b, xc);
    }
    // 3. x_dbl = xc @ x_proj_w^T  (double-buffered, 2-way K split)
    {
        dim3 grid(MROWS/32, 2);
        gemm_xdbl<<<grid, 256>>>(xc, x_proj_w, xdbl);
    }
    // 4. dt = softplus(dt_low @ dt_proj_w^T + b)
    {
        dim3 grid(DI/128, MROWS/64);
        gemm_dt<<<grid, 256>>>(xdbl, dt_proj_w, dt_proj_b, dtb);
    }
    // 5. chunked selective scan (8 lanes/unit)
    scan_pass1<<<(NCHAN*NCH)/32, 256>>>(xdbl, dtb, xc, A_log, Pb, Hb);
    scan_combine<<<(NCHAN*DS + 255)/256, 256>>>(Pb, Hb, Hinb);
    scan_pass2<<<(NCHAN*NCH)/32, 256>>>(xdbl, dtb, xc, zb, A_log, D_param, Hinb, yb);
    // 6. out = y @ out_proj_w^T   (tf32 tensor cores, cp.async)
    {
        dim3 grid(DM/128, MROWS/128);
        gemm_tf32<0><<<grid, 256, GEMM_SMEM>>>(yb, out_proj_w, out, nullptr, MROWS, DM, DI);
    }
}

// round 5
// speedup vs baseline: 1.5021x; 1.0274x over previous
#include <cuda_runtime.h>
#include <cuda_bf16.h>
#include <cstdint>

// Problem constants
static constexpr int BB = 2;
static constexpr int LSEQ = 2048;
static constexpr int DM = 768;        // d_model
static constexpr int DI = 1536;       // d_inner
static constexpr int DS = 16;         // d_state
static constexpr int RK = 48;         // dt_rank
static constexpr int XD = RK + 2*DS;  // 80
static constexpr int MROWS = BB * LSEQ;  // 4096

// Scan chunking
static constexpr int NCH = 8;
static constexpr int CHUNK = LSEQ / NCH;   // 256
static constexpr int NCHAN = BB * DI;      // 3072

// Scratch (no cudaMalloc allowed)
__device__ float g_xp  [MROWS * DI];
__device__ float g_z   [MROWS * DI];
__device__ float g_xc  [MROWS * DI];
__device__ float g_xdbl[MROWS * XD];
__device__ float g_dt  [MROWS * DI];
__device__ float g_y   [MROWS * DI];
__device__ float g_P   [NCHAN * NCH * DS];
__device__ float g_H   [NCHAN * NCH * DS];
__device__ float g_Hin [NCHAN * NCH * DS];
// tf32-prerounded operands
__device__ float g_xtf [MROWS * DM];
__device__ float g_w1tf[2 * DI * DM];
__device__ float g_w6tf[DM * DI];

__device__ __forceinline__ float siluf(float v) {
    return v / (1.f + __expf(-v));
}
__device__ __forceinline__ float softplusf(float v) {
    if (v > 20.f) return v;
    if (v < -20.f) return __expf(v);
    return log1pf(__expf(v));
}
__device__ __forceinline__ uint32_t f2tf32(float f) {
    uint32_t r;
    asm("cvt.rna.tf32.f32 %0, %1;" : "=r"(r) : "f"(f));
    return r;
}
__device__ __forceinline__ float ex2f(float x) {
    float r;
    asm("ex2.approx.f32 %0, %1;" : "=f"(r) : "f"(x));
    return r;
}
__device__ __forceinline__ void mma_tf32(float c[4], uint32_t a0, uint32_t a1,
                                         uint32_t a2, uint32_t a3,
                                         uint32_t b0, uint32_t b1) {
    asm volatile(
        "mma.sync.aligned.m16n8k8.row.col.f32.tf32.tf32.f32 "
        "{%0,%1,%2,%3}, {%4,%5,%6,%7}, {%8,%9}, {%0,%1,%2,%3};"
        : "+f"(c[0]), "+f"(c[1]), "+f"(c[2]), "+f"(c[3])
        : "r"(a0), "r"(a1), "r"(a2), "r"(a3), "r"(b0), "r"(b1));
}
__device__ __forceinline__ void cp16(uint32_t saddr, const float* g) {
    asm volatile("cp.async.cg.shared.global [%0], [%1], 16;" :: "r"(saddr), "l"(g));
}
#define CP_COMMIT() asm volatile("cp.async.commit_group;")
#define CP_WAIT(n)  asm volatile("cp.async.wait_group %0;" :: "n"(n))

// ---------------------------------------------------------------------------
// Pre-round x, in_proj_w, out_proj_w to tf32 (bitwise same as in-fragment cvt)
// ---------------------------------------------------------------------------
__global__ __launch_bounds__(256)
void prep_tf32(const float4* __restrict__ x, const float4* __restrict__ w1,
               const float4* __restrict__ w6,
               float4* __restrict__ xt, float4* __restrict__ w1t,
               float4* __restrict__ w6t)
{
    const int N1 = MROWS*DM/4, N2 = 2*DI*DM/4, N3 = DM*DI/4;
    int i = blockIdx.x * 256 + threadIdx.x;
    float4 v; float4* o;
    if (i < N1)            { v = x[i];        o = xt  + i; }
    else if (i < N1+N2)    { v = w1[i-N1];    o = w1t + (i-N1); }
    else if (i < N1+N2+N3) { v = w6[i-N1-N2]; o = w6t + (i-N1-N2); }
    else return;
    v.x = __uint_as_float(f2tf32(v.x));
    v.y = __uint_as_float(f2tf32(v.y));
    v.z = __uint_as_float(f2tf32(v.z));
    v.w = __uint_as_float(f2tf32(v.w));
    *o = v;
}

// ---------------------------------------------------------------------------
// tf32 tensor-core GEMM, 3-stage cp.async ring, operands pre-rounded to tf32.
// C[M,N] = A[M,K] @ W[N,K]^T.  Block 128x128, k-tile 32, 8 warps (2M x 4N).
// Dynamic smem: 3 stages x (128x36 A + 128x36 W) u32 = 110592 B.
// ONE __syncthreads per k-tile.
// EPI==0: plain store to C0 (ld = N); EPI==1: split at DI -> C0 / C1.
// Requires M%128==0, N%128==0, K%32==0, (K/32)%1.
// ---------------------------------------------------------------------------
#define ASu(b,r,k) smu[(b)*9216 + (r)*36 + (k)]
#define WSu(b,r,k) smu[(b)*9216 + 4608 + (r)*36 + (k)]

template<int EPI>
__global__ __launch_bounds__(256, 2)
void gemm_tf32(const float* __restrict__ A, const float* __restrict__ W,
               float* __restrict__ C0, float* __restrict__ C1,
               int M, int N, int K)
{
    extern __shared__ uint32_t smu[];
    uint32_t sbase;
    {
        uint64_t tmp = __cvta_generic_to_shared(smu);
        sbase = (uint32_t)tmp;
    }

    const int tid  = threadIdx.x;
    const int lane = tid & 31;
    const int wid  = tid >> 5;
    const int wm   = wid & 1;          // 0..1  (M)
    const int wn   = wid >> 1;         // 0..3  (N)
    const int bm   = blockIdx.y * 128;
    const int bn   = blockIdx.x * 128;

    const int ldr = tid >> 3;          // 0..31
    const int ldc = (tid & 7) * 4;     // col*4
    const int g   = lane >> 2;
    const int q4  = lane & 3;

    float c[4][4][4];
#pragma unroll
    for (int i = 0; i < 4; ++i)
#pragma unroll
        for (int j = 0; j < 4; ++j)
#pragma unroll
            for (int q = 0; q < 4; ++q) c[i][j][q] = 0.f;

    const float* Abase = A + (size_t)bm * K + ldc;
    const float* Wbase = W + (size_t)bn * K + ldc;

#define ISSUE(k0, buf) {                                                     \
    _Pragma("unroll") for (int p = 0; p < 4; ++p) {                          \
        int r = ldr + p*32;                                                  \
        cp16(sbase + (uint32_t)(((buf)*9216 + r*36 + ldc))*4,                \
             Abase + (size_t)r * K + (k0));                                  \
        cp16(sbase + (uint32_t)(((buf)*9216 + 4608 + r*36 + ldc))*4,         \
             Wbase + (size_t)r * K + (k0)); } }

#define COMPUTE(buf, ks) {                                                   \
    const int kk = (ks)*8 + q4;                                              \
    uint32_t a[4][4], b[4][2];                                               \
    _Pragma("unroll") for (int mt = 0; mt < 4; ++mt) {                       \
        int r = wm*64 + mt*16 + g;                                           \
        a[mt][0] = ASu(buf, r, kk);                                          \
        a[mt][1] = ASu(buf, r+8, kk);                                        \
        a[mt][2] = ASu(buf, r, kk+4);                                        \
        a[mt][3] = ASu(buf, r+8, kk+4); }                                    \
    _Pragma("unroll") for (int nt = 0; nt < 4; ++nt) {                       \
        int n = wn*32 + nt*8 + g;                                            \
        b[nt][0] = WSu(buf, n, kk);                                          \
        b[nt][1] = WSu(buf, n, kk+4); }                                      \
    _Pragma("unroll") for (int mt = 0; mt < 4; ++mt)                         \
        _Pragma("unroll") for (int nt = 0; nt < 4; ++nt)                     \
            mma_tf32(c[mt][nt], a[mt][0], a[mt][1], a[mt][2], a[mt][3],     \
                     b[nt][0], b[nt][1]); }

    ISSUE(0, 0);
    CP_COMMIT();
    ISSUE(32, 1);
    CP_COMMIT();

    const int NT = K / 32;
    for (int t = 0; t < NT; ++t) {
        const int buf = t % 3;
        CP_WAIT(1);                 // group t complete (in-order retirement)
        __syncthreads();            // all warps done with buffer (t+2)%3
        if (t + 2 < NT) {
            ISSUE((t+2)*32, (t+2)%3);
        }
        CP_COMMIT();                // unconditional: keeps group accounting aligned
        COMPUTE(buf, 0);
        COMPUTE(buf, 1);
        COMPUTE(buf, 2);
        COMPUTE(buf, 3);
    }

    // epilogue
    const int q2 = (lane & 3) * 2;
    float* base;
    int ncol0, ldo;
    if (EPI == 0) { base = C0; ncol0 = bn; ldo = N; }
    else {
        base = (bn < DI) ? C0 : C1;
        ncol0 = (bn < DI) ? bn : (bn - DI);
        ldo = DI;
    }
#pragma unroll
    for (int mt = 0; mt < 4; ++mt) {
#pragma unroll
        for (int nt = 0; nt < 4; ++nt) {
            int row = bm + wm*64 + mt*16 + g;
            int col = ncol0 + wn*32 + nt*8 + q2;
            float2 v0 = make_float2(c[mt][nt][0], c[mt][nt][1]);
            float2 v1 = make_float2(c[mt][nt][2], c[mt][nt][3]);
            *(float2*)(base + (size_t)row * ldo + col) = v0;
            *(float2*)(base + (size_t)(row + 8) * ldo + col) = v1;
        }
    }
#undef ISSUE
#undef COMPUTE
}

// ---------------------------------------------------------------------------
// Depthwise causal conv1d (K=4, left-pad 3) + bias + SiLU, float4 over d
// ---------------------------------------------------------------------------
__global__ __launch_bounds__(256)
void conv_silu_kernel(const float* __restrict__ xp, const float* __restrict__ cw,
                      const float* __restrict__ cb, float* __restrict__ xc)
{
    int idx = blockIdx.x * blockDim.x + threadIdx.x;   // over MROWS*DI/4
    if (idx >= MROWS * DI / 4) return;
    int dq = idx % (DI/4);
    int row = idx / (DI/4);
    int l = row % LSEQ;
    int d = dq * 4;

    float4 wq0 = *(const float4*)(cw + d*4 + 0);
    float4 wq1 = *(const float4*)(cw + d*4 + 4);
    float4 wq2 = *(const float4*)(cw + d*4 + 8);
    float4 wq3 = *(const float4*)(cw + d*4 + 12);

    float4 acc = *(const float4*)(cb + d);
    const float* p = xp + (size_t)row * DI + d;

    if (l >= 3) {
        float4 v = *(const float4*)(p - 3*DI);
        acc.x = fmaf(v.x, wq0.x, acc.x); acc.y = fmaf(v.y, wq1.x, acc.y);
        acc.z = fmaf(v.z, wq2.x, acc.z); acc.w = fmaf(v.w, wq3.x, acc.w);
    }
    if (l >= 2) {
        float4 v = *(const float4*)(p - 2*DI);
        acc.x = fmaf(v.x, wq0.y, acc.x); acc.y = fmaf(v.y, wq1.y, acc.y);
        acc.z = fmaf(v.z, wq2.y, acc.z); acc.w = fmaf(v.w, wq3.y, acc.w);
    }
    if (l >= 1) {
        float4 v = *(const float4*)(p - 1*DI);
        acc.x = fmaf(v.x, wq0.z, acc.x); acc.y = fmaf(v.y, wq1.z, acc.y);
        acc.z = fmaf(v.z, wq2.z, acc.z); acc.w = fmaf(v.w, wq3.z, acc.w);
    }
    {
        float4 v = *(const float4*)(p);
        acc.x = fmaf(v.x, wq0.w, acc.x); acc.y = fmaf(v.y, wq1.w, acc.y);
        acc.z = fmaf(v.z, wq2.w, acc.z); acc.w = fmaf(v.w, wq3.w, acc.w);
    }
    float4 r = make_float4(siluf(acc.x), siluf(acc.y), siluf(acc.z), siluf(acc.w));
    *(float4*)(xc + (size_t)row * DI + d) = r;
}

// ---------------------------------------------------------------------------
// Zero g_xdbl (for atomic K-split accumulation)
// ---------------------------------------------------------------------------
__global__ __launch_bounds__(256)
void zero_xdbl(float4* __restrict__ x)
{
    int i = blockIdx.x * 256 + threadIdx.x;    // MROWS*XD/4 = 81920
    x[i] = make_float4(0.f, 0.f, 0.f, 0.f);
}

// ---------------------------------------------------------------------------
// x_dbl = xc @ x_proj_w^T   [4096,1536] x [80,1536]^T -> [4096,80]
// BM=64, 4x5 micro-tile (a-side via LDS.128), double-buffered, 2-way K split,
// atomicAdd epilogue (2 addends onto zero -> deterministic). grid = (64, 2).
// ---------------------------------------------------------------------------
__global__ __launch_bounds__(256)
void gemm_xdbl(const float* __restrict__ A, const float* __restrict__ W,
               float* __restrict__ C)
{
    __shared__ float As[2][32][68];
    __shared__ float Ws[2][32][81];
    const int tid = threadIdx.x;
    const int bm = blockIdx.x * 64;
    const int kbeg = blockIdx.y * (DI/2);
    const int tr = tid >> 4;      // 0..15 -> rows tr*4 .. tr*4+3
    const int tc = tid & 15;      // 0..15 -> cols tc*5 .. tc*5+4
    const int cc = tid & 31;      // k within tile
    const int r0 = tid >> 5;      // 0..7

    float acc[4][5];
#pragma unroll
    for (int i = 0; i < 4; ++i)
#pragma unroll
        for (int j = 0; j < 5; ++j) acc[i][j] = 0.f;

    float a_st[8], w_st[10];

#define XLOAD(k0) {                                                          \
    _Pragma("unroll") for (int p = 0; p < 8; ++p)                            \
        a_st[p] = A[(size_t)(bm + r0 + p*8) * DI + (k0) + cc];               \
    _Pragma("unroll") for (int p = 0; p < 10; ++p)                           \
        w_st[p] = W[(size_t)(r0 + p*8) * DI + (k0) + cc]; }
#define XSTORE(buf) {                                                        \
    _Pragma("unroll") for (int p = 0; p < 8; ++p)                            \
        As[buf][cc][r0 + p*8] = a_st[p];                                     \
    _Pragma("unroll") for (int p = 0; p < 10; ++p)                           \
        Ws[buf][cc][r0 + p*8] = w_st[p]; }

    XLOAD(kbeg);
    XSTORE(0);
    __syncthreads();

    const int NT = (DI/2) / 32;   // 24
    for (int t = 0; t < NT; ++t) {
        const int cur = t & 1;
        if (t + 1 < NT) XLOAD(kbeg + (t+1)*32);
#pragma unroll
        for (int k = 0; k < 32; ++k) {
            float4 a4 = *(const float4*)&As[cur][k][tr*4];
            float a[4] = {a4.x, a4.y, a4.z, a4.w};
#pragma unroll
            for (int j = 0; j < 5; ++j) {
                float w = Ws[cur][k][tc*5 + j];
#pragma unroll
                for (int i = 0; i < 4; ++i)
                    acc[i][j] = fmaf(a[i], w, acc[i][j]);
            }
        }
        if (t + 1 < NT) {
            XSTORE(cur^1);
            __syncthreads();
        }
    }
#pragma unroll
    for (int i = 0; i < 4; ++i)
#pragma unroll
        for (int j = 0; j < 5; ++j)
            atomicAdd(&C[(size_t)(bm + tr*4 + i) * XD + tc*5 + j], acc[i][j]);
#undef XLOAD
#undef XSTORE
}

// ---------------------------------------------------------------------------
// dt = softplus( x_dbl[:, :48] @ dt_proj_w^T + b )  -> [4096,1536]
// Block: 64 rows x 128 cols, 256 threads, 8x4 micro-tile. grid = (12, 64)
// ---------------------------------------------------------------------------
__global__ __launch_bounds__(256)
void gemm_dt(const float* __restrict__ xdbl, const float* __restrict__ Wt,
             const float* __restrict__ bt, float* __restrict__ dt)
{
    __shared__ float s_inT[48][68];   // [q][row]
    __shared__ float s_w[48][132];    // [q][col]
    const int tid = threadIdx.x;
    const int m0 = blockIdx.y * 64;
    const int n0 = blockIdx.x * 128;

    for (int i = tid; i < 64*48; i += 256) {
        int r = i / 48, q = i % 48;
        s_inT[q][r] = xdbl[(size_t)(m0 + r) * XD + q];
    }
    for (int i = tid; i < 128*48; i += 256) {
        int col = i / 48, q = i % 48;
        s_w[q][col] = Wt[(size_t)(n0 + col) * RK + q];
    }
    __syncthreads();

    const int col = (tid & 31) * 4;
    const int row0 = (tid >> 5) * 8;

    float acc[8][4];
    {
        float4 b4 = *(const float4*)(bt + n0 + col);
#pragma unroll
        for (int r = 0; r < 8; ++r) {
            acc[r][0] = b4.x; acc[r][1] = b4.y; acc[r][2] = b4.z; acc[r][3] = b4.w;
        }
    }
#pragma unroll
    for (int q = 0; q < 48; ++q) {
        float4 a0 = *(const float4*)&s_inT[q][row0];
        float4 a1 = *(const float4*)&s_inT[q][row0 + 4];
        float4 w4 = *(const float4*)&s_w[q][col];
        float a[8] = {a0.x,a0.y,a0.z,a0.w,a1.x,a1.y,a1.z,a1.w};
#pragma unroll
        for (int r = 0; r < 8; ++r) {
            acc[r][0] = fmaf(a[r], w4.x, acc[r][0]);
            acc[r][1] = fmaf(a[r], w4.y, acc[r][1]);
            acc[r][2] = fmaf(a[r], w4.z, acc[r][2]);
            acc[r][3] = fmaf(a[r], w4.w, acc[r][3]);
        }
    }
#pragma unroll
    for (int r = 0; r < 8; ++r) {
        float* p = dt + (size_t)(m0 + row0 + r) * DI + n0 + col;
        float4 v = make_float4(softplusf(acc[r][0]), softplusf(acc[r][1]),
                               softplusf(acc[r][2]), softplusf(acc[r][3]));
        *(float4*)p = v;
    }
}

// ---------------------------------------------------------------------------
// Chunked selective scan, pass 1. 8 lanes per (channel, chunk) unit, lane
// handles states {2s, 2s+1}. A pre-scaled by log2(e) -> ex2 in the loop.
// ---------------------------------------------------------------------------
__global__ __launch_bounds__(256)
void scan_pass1(const float* __restrict__ xdbl, const float* __restrict__ dt,
                const float* __restrict__ xc, const float* __restrict__ A_log,
                float* __restrict__ P, float* __restrict__ H)
{
    const float LOG2E = 1.4426950408889634f;
    const int s = threadIdx.x & 7;
    const int unit = blockIdx.x * 32 + (threadIdx.x >> 3);
    const int ch = unit >> 3;          // 0..3071
    const int c  = unit & 7;           // chunk
    const int b = ch / DI;
    const int d = ch % DI;

    float2 Alog2 = *(const float2*)(A_log + d*DS + 2*s);
    const float A0 = -__expf(Alog2.x) * LOG2E;
    const float A1 = -__expf(Alog2.y) * LOG2E;
    float h0 = 0.f, h1 = 0.f, P0 = 1.f, P1 = 1.f;

    const int row0 = b * LSEQ + c * CHUNK;
    const float* dt_p = dt + (size_t)row0 * DI + d;
    const float* xc_p = xc + (size_t)row0 * DI + d;
    const float* xd_p = xdbl + (size_t)row0 * XD;

#pragma unroll 4
    for (int l = 0; l < CHUNK; ++l) {
        float dtv = __ldg(dt_p);
        float xcv = __ldg(xc_p);
        float2 Bv = *(const float2*)(xd_p + RK + 2*s);
        float a0 = ex2f(dtv * A0);
        float a1 = ex2f(dtv * A1);
        float bx = dtv * xcv;
        P0 *= a0; P1 *= a1;
        h0 = fmaf(a0, h0, bx * Bv.x);
        h1 = fmaf(a1, h1, bx * Bv.y);
        dt_p += DI; xc_p += DI; xd_p += XD;
    }
    *(float2*)(P + unit * DS + 2*s) = make_float2(P0, P1);
    *(float2*)(H + unit * DS + 2*s) = make_float2(h0, h1);
}

// ---------------------------------------------------------------------------
// Combine: serial scan over the 8 chunk transitions per (channel, state).
// ---------------------------------------------------------------------------
__global__ __launch_bounds__(256)
void scan_combine(const float* __restrict__ P, const float* __restrict__ H,
                  float* __restrict__ Hin)
{
    int idx = blockIdx.x * blockDim.x + threadIdx.x;
    if (idx >= NCHAN * DS) return;
    int ch = idx >> 4;
    int s = idx & 15;
    float run = 0.f;
#pragma unroll
    for (int c = 0; c < NCH; ++c) {
        int o = (ch * NCH + c) * DS + s;
        Hin[o] = run;
        run = fmaf(P[o], run, H[o]);
    }
}

// ---------------------------------------------------------------------------
// Pass 2: replay from correct incoming state; y = (sum_s h*C + xc*D)*silu(z),
// stored pre-rounded to tf32 (bitwise same as gemm6's fragment cvt).
// ---------------------------------------------------------------------------
__global__ __launch_bounds__(256)
void scan_pass2(const float* __restrict__ xdbl, const float* __restrict__ dt,
                const float* __restrict__ xc, const float* __restrict__ z,
                const float* __restrict__ A_log, const float* __restrict__ Dp,
                const float* __restrict__ Hin, float* __restrict__ y)
{
    const float LOG2E = 1.4426950408889634f;
    const int s = threadIdx.x & 7;
    const int unit = blockIdx.x * 32 + (threadIdx.x >> 3);
    const int ch = unit >> 3;
    const int c  = unit & 7;
    const int b = ch / DI;
    const int d = ch % DI;

    float2 Alog2 = *(const float2*)(A_log + d*DS + 2*s);
    const float A0 = -__expf(Alog2.x) * LOG2E;
    const float A1 = -__expf(Alog2.y) * LOG2E;
    const float Dv = Dp[d];
    float2 h2 = *(const float2*)(Hin + unit * DS + 2*s);
    float h0 = h2.x, h1 = h2.y;

    const int row0 = b * LSEQ + c * CHUNK;
    const float* dt_p = dt + (size_t)row0 * DI + d;
    const float* xc_p = xc + (size_t)row0 * DI + d;
    const float* z_p  = z  + (size_t)row0 * DI + d;
    const float* xd_p = xdbl + (size_t)row0 * XD;
    float* y_p = y + (size_t)row0 * DI + d;

#pragma unroll 4
    for (int l = 0; l < CHUNK; ++l) {
        float dtv = __ldg(dt_p);
        float xcv = __ldg(xc_p);
        float2 Bv = *(const float2*)(xd_p + RK + 2*s);
        float2 Cv = *(const float2*)(xd_p + RK + DS + 2*s);

        float a0 = ex2f(dtv * A0);
        float a1 = ex2f(dtv * A1);
        float bx = dtv * xcv;
        h0 = fmaf(a0, h0, bx * Bv.x);
        h1 = fmaf(a1, h1, bx * Bv.y);
        float p = fmaf(h0, Cv.x, h1 * Cv.y);
        p += __shfl_xor_sync(0xffffffffu, p, 1);
        p += __shfl_xor_sync(0xffffffffu, p, 2);
        p += __shfl_xor_sync(0xffffffffu, p, 4);
        if (s == 0) {
            float zv = __ldg(z_p);
            float val = (p + xcv * Dv) * siluf(zv);
            *y_p = __uint_as_float(f2tf32(val));
        }
        dt_p += DI; xc_p += DI; z_p += DI; y_p += DI; xd_p += XD;
    }
}

// ---------------------------------------------------------------------------
extern "C" void kernel_launch(void* const* d_in, const int* in_sizes, int n_in,
                              void* d_out, int out_size)
{
    const float* x          = (const float*)d_in[0];
    const float* in_proj_w  = (const float*)d_in[1];
    const float* conv_w     = (const float*)d_in[2];
    const float* conv_b     = (const float*)d_in[3];
    const float* A_log      = (const float*)d_in[4];
    const float* D_param    = (const float*)d_in[5];
    const float* x_proj_w   = (const float*)d_in[6];
    const float* dt_proj_w  = (const float*)d_in[7];
    const float* dt_proj_b  = (const float*)d_in[8];
    const float* out_proj_w = (const float*)d_in[9];
    float* out = (float*)d_out;

    float *xp, *zb, *xc, *xdbl, *dtb, *yb, *Pb, *Hb, *Hinb, *xtf, *w1tf, *w6tf;
    cudaGetSymbolAddress((void**)&xp,   g_xp);
    cudaGetSymbolAddress((void**)&zb,   g_z);
    cudaGetSymbolAddress((void**)&xc,   g_xc);
    cudaGetSymbolAddress((void**)&xdbl, g_xdbl);
    cudaGetSymbolAddress((void**)&dtb,  g_dt);
    cudaGetSymbolAddress((void**)&yb,   g_y);
    cudaGetSymbolAddress((void**)&Pb,   g_P);
    cudaGetSymbolAddress((void**)&Hb,   g_H);
    cudaGetSymbolAddress((void**)&Hinb, g_Hin);
    cudaGetSymbolAddress((void**)&xtf,  g_xtf);
    cudaGetSymbolAddress((void**)&w1tf, g_w1tf);
    cudaGetSymbolAddress((void**)&w6tf, g_w6tf);

    const int GEMM_SMEM = 3 * 2 * 128 * 36 * 4;   // 110592 B
    cudaFuncSetAttribute(gemm_tf32<0>, cudaFuncAttributeMaxDynamicSharedMemorySize, GEMM_SMEM);
    cudaFuncSetAttribute(gemm_tf32<1>, cudaFuncAttributeMaxDynamicSharedMemorySize, GEMM_SMEM);

    // 0a. pre-round x / in_proj_w / out_proj_w to tf32
    {
        const int total4 = (MROWS*DM + 2*DI*DM + DM*DI) / 4;
        prep_tf32<<<(total4 + 255)/256, 256>>>(
            (const float4*)x, (const float4*)in_proj_w, (const float4*)out_proj_w,
            (float4*)xtf, (float4*)w1tf, (float4*)w6tf);
    }
    // 0b. zero x_dbl accumulator (atomic K-split target)
    zero_xdbl<<<(MROWS*XD/4)/256, 256>>>((float4*)xdbl);
    // 1. xz = x @ in_proj_w^T, split -> xp, z
    {
        dim3 grid(2*DI/128, MROWS/128);
        gemm_tf32<1><<<grid, 256, GEMM_SMEM>>>(xtf, w1tf, xp, zb, MROWS, 2*DI, DM);
    }
    // 2. causal depthwise conv + bias + SiLU -> xc
    {
        int total = MROWS * DI / 4;
        conv_silu_kernel<<<(total + 255)/256, 256>>>(xp, conv_w, conv_b, xc);
    }
    // 3. x_dbl = xc @ x_proj_w^T  (BM=64, 4x5, double-buffered, 2-way K split)
    {
        dim3 grid(MROWS/64, 2);
        gemm_xdbl<<<grid, 256>>>(xc, x_proj_w, xdbl);
    }
    // 4. dt = softplus(dt_low @ dt_proj_w^T + b)
    {
        dim3 grid(DI/128, MROWS/64);
        gemm_dt<<<grid, 256>>>(xdbl, dt_proj_w, dt_proj_b, dtb);
    }
    // 5. chunked selective scan
    scan_pass1<<<(NCHAN*NCH)/32, 256>>>(xdbl, dtb, xc, A_log, Pb, Hb);
    scan_combine<<<(NCHAN*DS + 255)/256, 256>>>(Pb, Hb, Hinb);
    scan_pass2<<<(NCHAN*NCH)/32, 256>>>(xdbl, dtb, xc, zb, A_log, D_param, Hinb, yb);
    // 6. out = y @ out_proj_w^T
    {
        dim3 grid(DM/128, MROWS/128);
        gemm_tf32<0><<<grid, 256, GEMM_SMEM>>>(yb, w6tf, out, nullptr, MROWS, DM, DI);
    }
}

// round 7
// speedup vs baseline: 1.8510x; 1.2323x over previous
#include <cuda_runtime.h>
#include <cuda_fp16.h>
#include <cuda_bf16.h>
#include <cstdint>

// Problem constants
static constexpr int BB = 2;
static constexpr int LSEQ = 2048;
static constexpr int DM = 768;        // d_model
static constexpr int DI = 1536;       // d_inner
static constexpr int DS = 16;         // d_state
static constexpr int RK = 48;         // dt_rank
static constexpr int XD = RK + 2*DS;  // 80
static constexpr int MROWS = BB * LSEQ;  // 4096

// Scan chunking
static constexpr int NCH = 8;
static constexpr int CHUNK = LSEQ / NCH;   // 256
static constexpr int NCHAN = BB * DI;      // 3072

// Scratch (no cudaMalloc allowed)
__device__ float g_xp  [MROWS * DI];
__device__ float g_z   [MROWS * DI];
__device__ float g_xc  [MROWS * DI];
__device__ float g_xdbl[MROWS * XD];
__device__ float g_dt  [MROWS * DI];
__device__ float g_P   [NCHAN * NCH * DS];
__device__ float g_H   [NCHAN * NCH * DS];
__device__ float g_Hin [NCHAN * NCH * DS];
// fp16 operands
__device__ __half g_xh [MROWS * DM];
__device__ __half g_w1h[2 * DI * DM];
__device__ __half g_w6h[DM * DI];
__device__ __half g_yh [MROWS * DI];

__device__ __forceinline__ float siluf(float v) {
    return v / (1.f + __expf(-v));
}
__device__ __forceinline__ float softplusf(float v) {
    if (v > 20.f) return v;
    if (v < -20.f) return __expf(v);
    return log1pf(__expf(v));
}
__device__ __forceinline__ float ex2f(float x) {
    float r;
    asm("ex2.approx.f32 %0, %1;" : "=f"(r) : "f"(x));
    return r;
}
__device__ __forceinline__ void cp16(uint32_t saddr, const void* g) {
    asm volatile("cp.async.cg.shared.global [%0], [%1], 16;" :: "r"(saddr), "l"(g));
}
#define CP_COMMIT() asm volatile("cp.async.commit_group;")
#define CP_WAIT(n)  asm volatile("cp.async.wait_group %0;" :: "n"(n))

__device__ __forceinline__ void mma_fp16(float c[4], uint32_t a0, uint32_t a1,
                                         uint32_t a2, uint32_t a3,
                                         uint32_t b0, uint32_t b1) {
    asm volatile(
        "mma.sync.aligned.m16n8k16.row.col.f32.f16.f16.f32 "
        "{%0,%1,%2,%3}, {%4,%5,%6,%7}, {%8,%9}, {%0,%1,%2,%3};"
        : "+f"(c[0]), "+f"(c[1]), "+f"(c[2]), "+f"(c[3])
        : "r"(a0), "r"(a1), "r"(a2), "r"(a3), "r"(b0), "r"(b1));
}

// ---------------------------------------------------------------------------
// fp16 tensor-core GEMM, 3-stage cp.async ring: C[M,N] = A[M,K] @ W[N,K]^T
// Block 128x128, k-tile 64 halves, 8 warps (2M x 4N), warp tile 64x32,
// mma m16n8k16 (4 k-steps per tile). Smem stride 72 halves (conflict-free).
// Dynamic smem: 3 x (128*72 A + 128*72 W) halves = 110592 B.
// EPI==0: plain store to C0 (ld = N); EPI==1: split at DI -> C0 / C1.
// Requires M%128==0, N%128==0, K%64==0.
// ---------------------------------------------------------------------------
#define ASH(b,r,k) smh[(b)*18432 + (r)*72 + (k)]
#define WSH(b,r,k) smh[(b)*18432 + 9216 + (r)*72 + (k)]

template<int EPI>
__global__ __launch_bounds__(256, 2)
void gemm_fp16(const __half* __restrict__ A, const __half* __restrict__ W,
               float* __restrict__ C0, float* __restrict__ C1,
               int M, int N, int K)
{
    extern __shared__ __half smh[];
    uint32_t sbase;
    {
        uint64_t tmp = __cvta_generic_to_shared(smh);
        sbase = (uint32_t)tmp;
    }

    const int tid  = threadIdx.x;
    const int lane = tid & 31;
    const int wid  = tid >> 5;
    const int wm   = wid & 1;          // 0..1  (M)
    const int wn   = wid >> 1;         // 0..3  (N)
    const int bm   = blockIdx.y * 128;
    const int bn   = blockIdx.x * 128;

    const int ldr = tid >> 3;          // 0..31 (row within pass)
    const int ldc = (tid & 7) * 8;     // half-col (8 halves = 16B)
    const int g   = lane >> 2;
    const int q4  = lane & 3;

    float c[4][4][4];
#pragma unroll
    for (int i = 0; i < 4; ++i)
#pragma unroll
        for (int j = 0; j < 4; ++j)
#pragma unroll
            for (int q = 0; q < 4; ++q) c[i][j][q] = 0.f;

    const __half* Abase = A + (size_t)bm * K + ldc;
    const __half* Wbase = W + (size_t)bn * K + ldc;

#define ISSUE(k0, buf) {                                                     \
    _Pragma("unroll") for (int p = 0; p < 4; ++p) {                          \
        int r = ldr + p*32;                                                  \
        cp16(sbase + (uint32_t)(((buf)*18432 + r*72 + ldc))*2,               \
             Abase + (size_t)r * K + (k0));                                  \
        cp16(sbase + (uint32_t)(((buf)*18432 + 9216 + r*72 + ldc))*2,        \
             Wbase + (size_t)r * K + (k0)); } }

#define COMPUTE(buf, ks) {                                                   \
    const int kk = (ks)*16 + 2*q4;                                           \
    uint32_t a[4][4], b[4][2];                                               \
    _Pragma("unroll") for (int mt = 0; mt < 4; ++mt) {                       \
        int r = wm*64 + mt*16 + g;                                           \
        a[mt][0] = *(const uint32_t*)&ASH(buf, r,   kk);                     \
        a[mt][1] = *(const uint32_t*)&ASH(buf, r+8, kk);                     \
        a[mt][2] = *(const uint32_t*)&ASH(buf, r,   kk+8);                   \
        a[mt][3] = *(const uint32_t*)&ASH(buf, r+8, kk+8); }                 \
    _Pragma("unroll") for (int nt = 0; nt < 4; ++nt) {                       \
        int n = wn*32 + nt*8 + g;                                            \
        b[nt][0] = *(const uint32_t*)&WSH(buf, n, kk);                       \
        b[nt][1] = *(const uint32_t*)&WSH(buf, n, kk+8); }                   \
    _Pragma("unroll") for (int mt = 0; mt < 4; ++mt)                         \
        _Pragma("unroll") for (int nt = 0; nt < 4; ++nt)                     \
            mma_fp16(c[mt][nt], a[mt][0], a[mt][1], a[mt][2], a[mt][3],     \
                     b[nt][0], b[nt][1]); }

    ISSUE(0, 0);
    CP_COMMIT();
    ISSUE(64, 1);
    CP_COMMIT();

    const int NT = K / 64;
    for (int t = 0; t < NT; ++t) {
        const int buf = t % 3;
        CP_WAIT(1);                 // group t complete (in-order retirement)
        __syncthreads();            // all warps done with buffer (t+2)%3
        if (t + 2 < NT) {
            ISSUE((t+2)*64, (t+2)%3);
        }
        CP_COMMIT();                // unconditional: keeps group accounting aligned
        COMPUTE(buf, 0);
        COMPUTE(buf, 1);
        COMPUTE(buf, 2);
        COMPUTE(buf, 3);
    }

    // epilogue (same fragment layout as tf32 m16n8k8: c0,c1 row g; c2,c3 row g+8)
    const int q2 = (lane & 3) * 2;
    float* base;
    int ncol0, ldo;
    if (EPI == 0) { base = C0; ncol0 = bn; ldo = N; }
    else {
        base = (bn < DI) ? C0 : C1;
        ncol0 = (bn < DI) ? bn : (bn - DI);
        ldo = DI;
    }
#pragma unroll
    for (int mt = 0; mt < 4; ++mt) {
#pragma unroll
        for (int nt = 0; nt < 4; ++nt) {
            int row = bm + wm*64 + mt*16 + g;
            int col = ncol0 + wn*32 + nt*8 + q2;
            float2 v0 = make_float2(c[mt][nt][0], c[mt][nt][1]);
            float2 v1 = make_float2(c[mt][nt][2], c[mt][nt][3]);
            *(float2*)(base + (size_t)row * ldo + col) = v0;
            *(float2*)(base + (size_t)(row + 8) * ldo + col) = v1;
        }
    }
#undef ISSUE
#undef COMPUTE
}

// ---------------------------------------------------------------------------
// Convert x, in_proj_w, out_proj_w to fp16
// ---------------------------------------------------------------------------
__global__ __launch_bounds__(256)
void prep_fp16(const float4* __restrict__ x, const float4* __restrict__ w1,
               const float4* __restrict__ w6,
               __half* __restrict__ xh, __half* __restrict__ w1h,
               __half* __restrict__ w6h)
{
    const int N1 = MROWS*DM/4, N2 = 2*DI*DM/4, N3 = DM*DI/4;
    int i = blockIdx.x * 256 + threadIdx.x;
    float4 v; __half* o; int off;
    if (i < N1)            { v = x[i];        o = xh;  off = i*4; }
    else if (i < N1+N2)    { v = w1[i-N1];    o = w1h; off = (i-N1)*4; }
    else if (i < N1+N2+N3) { v = w6[i-N1-N2]; o = w6h; off = (i-N1-N2)*4; }
    else return;
    __half2* o2 = (__half2*)(o + off);
    o2[0] = __floats2half2_rn(v.x, v.y);
    o2[1] = __floats2half2_rn(v.z, v.w);
}

// ---------------------------------------------------------------------------
// Depthwise causal conv1d (K=4, left-pad 3) + bias + SiLU
// Each thread: 4 consecutive l positions x 4 channels (float4).
// Loads 7 input rows instead of 16 -> ~55% fewer L1 wavefronts.
// ---------------------------------------------------------------------------
__global__ __launch_bounds__(256)
void conv_silu_kernel(const float* __restrict__ xp, const float* __restrict__ cw,
                      const float* __restrict__ cb, float* __restrict__ xc)
{
    const int NDQ = DI / 4;
    int idx = blockIdx.x * blockDim.x + threadIdx.x;   // over (MROWS/4)*NDQ
    if (idx >= (MROWS/4) * NDQ) return;
    int dq = idx % NDQ;
    int rg = idx / NDQ;                 // row group
    int b  = rg / (LSEQ/4);
    int l0 = (rg % (LSEQ/4)) * 4;
    int d  = dq * 4;

    // per-channel tap vectors
    float4 wq0 = *(const float4*)(cw + d*4 + 0);   // channel d:   taps 0..3
    float4 wq1 = *(const float4*)(cw + d*4 + 4);
    float4 wq2 = *(const float4*)(cw + d*4 + 8);
    float4 wq3 = *(const float4*)(cw + d*4 + 12);
    float4 bias = *(const float4*)(cb + d);

    const float* base = xp + ((size_t)(b * LSEQ + l0)) * DI + d;

    float4 in[7];
#pragma unroll
    for (int j = 0; j < 7; ++j) {
        int l = l0 - 3 + j;
        if (l >= 0) in[j] = *(const float4*)(base + (size_t)(j - 3) * DI);
        else        in[j] = make_float4(0.f, 0.f, 0.f, 0.f);
    }

    float* outp = xc + ((size_t)(b * LSEQ + l0)) * DI + d;
#pragma unroll
    for (int i = 0; i < 4; ++i) {
        float4 acc = bias;
        // taps 0..3 correspond to rows l0+i-3 .. l0+i -> in[i] .. in[i+3]
        acc.x = fmaf(in[i+0].x, wq0.x, acc.x); acc.y = fmaf(in[i+0].y, wq1.x, acc.y);
        acc.z = fmaf(in[i+0].z, wq2.x, acc.z); acc.w = fmaf(in[i+0].w, wq3.x, acc.w);
        acc.x = fmaf(in[i+1].x, wq0.y, acc.x); acc.y = fmaf(in[i+1].y, wq1.y, acc.y);
        acc.z = fmaf(in[i+1].z, wq2.y, acc.z); acc.w = fmaf(in[i+1].w, wq3.y, acc.w);
        acc.x = fmaf(in[i+2].x, wq0.z, acc.x); acc.y = fmaf(in[i+2].y, wq1.z, acc.y);
        acc.z = fmaf(in[i+2].z, wq2.z, acc.z); acc.w = fmaf(in[i+2].w, wq3.z, acc.w);
        acc.x = fmaf(in[i+3].x, wq0.w, acc.x); acc.y = fmaf(in[i+3].y, wq1.w, acc.y);
        acc.z = fmaf(in[i+3].z, wq2.w, acc.z); acc.w = fmaf(in[i+3].w, wq3.w, acc.w);
        float4 r = make_float4(siluf(acc.x), siluf(acc.y), siluf(acc.z), siluf(acc.w));
        *(float4*)(outp + (size_t)i * DI) = r;
    }
}

// ---------------------------------------------------------------------------
__global__ __launch_bounds__(256)
void zero_xdbl(float4* __restrict__ x)
{
    int i = blockIdx.x * 256 + threadIdx.x;
    x[i] = make_float4(0.f, 0.f, 0.f, 0.f);
}

// ---------------------------------------------------------------------------
// x_dbl = xc @ x_proj_w^T   [4096,1536] x [80,1536]^T -> [4096,80]
// BM=64, 4x5 micro-tile, double-buffered, 2-way K split, atomicAdd epilogue.
// ---------------------------------------------------------------------------
__global__ __launch_bounds__(256)
void gemm_xdbl(const float* __restrict__ A, const float* __restrict__ W,
               float* __restrict__ C)
{
    __shared__ float As[2][32][68];
    __shared__ float Ws[2][32][81];
    const int tid = threadIdx.x;
    const int bm = blockIdx.x * 64;
    const int kbeg = blockIdx.y * (DI/2);
    const int tr = tid >> 4;
    const int tc = tid & 15;
    const int cc = tid & 31;
    const int r0 = tid >> 5;

    float acc[4][5];
#pragma unroll
    for (int i = 0; i < 4; ++i)
#pragma unroll
        for (int j = 0; j < 5; ++j) acc[i][j] = 0.f;

    float a_st[8], w_st[10];

#define XLOAD(k0) {                                                          \
    _Pragma("unroll") for (int p = 0; p < 8; ++p)                            \
        a_st[p] = A[(size_t)(bm + r0 + p*8) * DI + (k0) + cc];               \
    _Pragma("unroll") for (int p = 0; p < 10; ++p)                           \
        w_st[p] = W[(size_t)(r0 + p*8) * DI + (k0) + cc]; }
#define XSTORE(buf) {                                                        \
    _Pragma("unroll") for (int p = 0; p < 8; ++p)                            \
        As[buf][cc][r0 + p*8] = a_st[p];                                     \
    _Pragma("unroll") for (int p = 0; p < 10; ++p)                           \
        Ws[buf][cc][r0 + p*8] = w_st[p]; }

    XLOAD(kbeg);
    XSTORE(0);
    __syncthreads();

    const int NT = (DI/2) / 32;
    for (int t = 0; t < NT; ++t) {
        const int cur = t & 1;
        if (t + 1 < NT) XLOAD(kbeg + (t+1)*32);
#pragma unroll
        for (int k = 0; k < 32; ++k) {
            float4 a4 = *(const float4*)&As[cur][k][tr*4];
            float a[4] = {a4.x, a4.y, a4.z, a4.w};
#pragma unroll
            for (int j = 0; j < 5; ++j) {
                float w = Ws[cur][k][tc*5 + j];
#pragma unroll
                for (int i = 0; i < 4; ++i)
                    acc[i][j] = fmaf(a[i], w, acc[i][j]);
            }
        }
        if (t + 1 < NT) {
            XSTORE(cur^1);
            __syncthreads();
        }
    }
#pragma unroll
    for (int i = 0; i < 4; ++i)
#pragma unroll
        for (int j = 0; j < 5; ++j)
            atomicAdd(&C[(size_t)(bm + tr*4 + i) * XD + tc*5 + j], acc[i][j]);
#undef XLOAD
#undef XSTORE
}

// ---------------------------------------------------------------------------
// dt = softplus( x_dbl[:, :48] @ dt_proj_w^T + b )  -> [4096,1536]
// ---------------------------------------------------------------------------
__global__ __launch_bounds__(256)
void gemm_dt(const float* __restrict__ xdbl, const float* __restrict__ Wt,
             const float* __restrict__ bt, float* __restrict__ dt)
{
    __shared__ float s_inT[48][68];
    __shared__ float s_w[48][132];
    const int tid = threadIdx.x;
    const int m0 = blockIdx.y * 64;
    const int n0 = blockIdx.x * 128;

    for (int i = tid; i < 64*48; i += 256) {
        int r = i / 48, q = i % 48;
        s_inT[q][r] = xdbl[(size_t)(m0 + r) * XD + q];
    }
    for (int i = tid; i < 128*48; i += 256) {
        int col = i / 48, q = i % 48;
        s_w[q][col] = Wt[(size_t)(n0 + col) * RK + q];
    }
    __syncthreads();

    const int col = (tid & 31) * 4;
    const int row0 = (tid >> 5) * 8;

    float acc[8][4];
    {
        float4 b4 = *(const float4*)(bt + n0 + col);
#pragma unroll
        for (int r = 0; r < 8; ++r) {
            acc[r][0] = b4.x; acc[r][1] = b4.y; acc[r][2] = b4.z; acc[r][3] = b4.w;
        }
    }
#pragma unroll
    for (int q = 0; q < 48; ++q) {
        float4 a0 = *(const float4*)&s_inT[q][row0];
        float4 a1 = *(const float4*)&s_inT[q][row0 + 4];
        float4 w4 = *(const float4*)&s_w[q][col];
        float a[8] = {a0.x,a0.y,a0.z,a0.w,a1.x,a1.y,a1.z,a1.w};
#pragma unroll
        for (int r = 0; r < 8; ++r) {
            acc[r][0] = fmaf(a[r], w4.x, acc[r][0]);
            acc[r][1] = fmaf(a[r], w4.y, acc[r][1]);
            acc[r][2] = fmaf(a[r], w4.z, acc[r][2]);
            acc[r][3] = fmaf(a[r], w4.w, acc[r][3]);
        }
    }
#pragma unroll
    for (int r = 0; r < 8; ++r) {
        float* p = dt + (size_t)(m0 + row0 + r) * DI + n0 + col;
        float4 v = make_float4(softplusf(acc[r][0]), softplusf(acc[r][1]),
                               softplusf(acc[r][2]), softplusf(acc[r][3]));
        *(float4*)p = v;
    }
}

// ---------------------------------------------------------------------------
// Chunked selective scan, pass 1. 8 lanes/unit, 2 states/lane, ex2.
// ---------------------------------------------------------------------------
__global__ __launch_bounds__(256)
void scan_pass1(const float* __restrict__ xdbl, const float* __restrict__ dt,
                const float* __restrict__ xc, const float* __restrict__ A_log,
                float* __restrict__ P, float* __restrict__ H)
{
    const float LOG2E = 1.4426950408889634f;
    const int s = threadIdx.x & 7;
    const int unit = blockIdx.x * 32 + (threadIdx.x >> 3);
    const int ch = unit >> 3;
    const int c  = unit & 7;
    const int b = ch / DI;
    const int d = ch % DI;

    float2 Alog2 = *(const float2*)(A_log + d*DS + 2*s);
    const float A0 = -__expf(Alog2.x) * LOG2E;
    const float A1 = -__expf(Alog2.y) * LOG2E;
    float h0 = 0.f, h1 = 0.f, P0 = 1.f, P1 = 1.f;

    const int row0 = b * LSEQ + c * CHUNK;
    const float* dt_p = dt + (size_t)row0 * DI + d;
    const float* xc_p = xc + (size_t)row0 * DI + d;
    const float* xd_p = xdbl + (size_t)row0 * XD;

#pragma unroll 4
    for (int l = 0; l < CHUNK; ++l) {
        float dtv = __ldg(dt_p);
        float xcv = __ldg(xc_p);
        float2 Bv = *(const float2*)(xd_p + RK + 2*s);
        float a0 = ex2f(dtv * A0);
        float a1 = ex2f(dtv * A1);
        float bx = dtv * xcv;
        P0 *= a0; P1 *= a1;
        h0 = fmaf(a0, h0, bx * Bv.x);
        h1 = fmaf(a1, h1, bx * Bv.y);
        dt_p += DI; xc_p += DI; xd_p += XD;
    }
    *(float2*)(P + unit * DS + 2*s) = make_float2(P0, P1);
    *(float2*)(H + unit * DS + 2*s) = make_float2(h0, h1);
}

// ---------------------------------------------------------------------------
__global__ __launch_bounds__(256)
void scan_combine(const float* __restrict__ P, const float* __restrict__ H,
                  float* __restrict__ Hin)
{
    int idx = blockIdx.x * blockDim.x + threadIdx.x;
    if (idx >= NCHAN * DS) return;
    int ch = idx >> 4;
    int s = idx & 15;
    float run = 0.f;
#pragma unroll
    for (int c = 0; c < NCH; ++c) {
        int o = (ch * NCH + c) * DS + s;
        Hin[o] = run;
        run = fmaf(P[o], run, H[o]);
    }
}

// ---------------------------------------------------------------------------
// Pass 2: y = (sum_s h*C + xc*D) * silu(z), emitted as fp16 for gemm6
// ---------------------------------------------------------------------------
__global__ __launch_bounds__(256)
void scan_pass2(const float* __restrict__ xdbl, const float* __restrict__ dt,
                const float* __restrict__ xc, const float* __restrict__ z,
                const float* __restrict__ A_log, const float* __restrict__ Dp,
                const float* __restrict__ Hin, __half* __restrict__ y)
{
    const float LOG2E = 1.4426950408889634f;
    const int s = threadIdx.x & 7;
    const int unit = blockIdx.x * 32 + (threadIdx.x >> 3);
    const int ch = unit >> 3;
    const int c  = unit & 7;
    const int b = ch / DI;
    const int d = ch % DI;

    float2 Alog2 = *(const float2*)(A_log + d*DS + 2*s);
    const float A0 = -__expf(Alog2.x) * LOG2E;
    const float A1 = -__expf(Alog2.y) * LOG2E;
    const float Dv = Dp[d];
    float2 h2 = *(const float2*)(Hin + unit * DS + 2*s);
    float h0 = h2.x, h1 = h2.y;

    const int row0 = b * LSEQ + c * CHUNK;
    const float* dt_p = dt + (size_t)row0 * DI + d;
    const float* xc_p = xc + (size_t)row0 * DI + d;
    const float* z_p  = z  + (size_t)row0 * DI + d;
    const float* xd_p = xdbl + (size_t)row0 * XD;
    __half* y_p = y + (size_t)row0 * DI + d;

#pragma unroll 4
    for (int l = 0; l < CHUNK; ++l) {
        float dtv = __ldg(dt_p);
        float xcv = __ldg(xc_p);
        float2 Bv = *(const float2*)(xd_p + RK + 2*s);
        float2 Cv = *(const float2*)(xd_p + RK + DS + 2*s);

        float a0 = ex2f(dtv * A0);
        float a1 = ex2f(dtv * A1);
        float bx = dtv * xcv;
        h0 = fmaf(a0, h0, bx * Bv.x);
        h1 = fmaf(a1, h1, bx * Bv.y);
        float p = fmaf(h0, Cv.x, h1 * Cv.y);
        p += __shfl_xor_sync(0xffffffffu, p, 1);
        p += __shfl_xor_sync(0xffffffffu, p, 2);
        p += __shfl_xor_sync(0xffffffffu, p, 4);
        if (s == 0) {
            float zv = __ldg(z_p);
            float val = (p + xcv * Dv) * siluf(zv);
            *y_p = __float2half_rn(val);
        }
        dt_p += DI; xc_p += DI; z_p += DI; y_p += DI; xd_p += XD;
    }
}

// ---------------------------------------------------------------------------
extern "C" void kernel_launch(void* const* d_in, const int* in_sizes, int n_in,
                              void* d_out, int out_size)
{
    const float* x          = (const float*)d_in[0];
    const float* in_proj_w  = (const float*)d_in[1];
    const float* conv_w     = (const float*)d_in[2];
    const float* conv_b     = (const float*)d_in[3];
    const float* A_log      = (const float*)d_in[4];
    const float* D_param    = (const float*)d_in[5];
    const float* x_proj_w   = (const float*)d_in[6];
    const float* dt_proj_w  = (const float*)d_in[7];
    const float* dt_proj_b  = (const float*)d_in[8];
    const float* out_proj_w = (const float*)d_in[9];
    float* out = (float*)d_out;

    float *xp, *zb, *xc, *xdbl, *dtb, *Pb, *Hb, *Hinb;
    __half *xh, *w1h, *w6h, *yh;
    cudaGetSymbolAddress((void**)&xp,   g_xp);
    cudaGetSymbolAddress((void**)&zb,   g_z);
    cudaGetSymbolAddress((void**)&xc,   g_xc);
    cudaGetSymbolAddress((void**)&xdbl, g_xdbl);
    cudaGetSymbolAddress((void**)&dtb,  g_dt);
    cudaGetSymbolAddress((void**)&Pb,   g_P);
    cudaGetSymbolAddress((void**)&Hb,   g_H);
    cudaGetSymbolAddress((void**)&Hinb, g_Hin);
    cudaGetSymbolAddress((void**)&xh,   g_xh);
    cudaGetSymbolAddress((void**)&w1h,  g_w1h);
    cudaGetSymbolAddress((void**)&w6h,  g_w6h);
    cudaGetSymbolAddress((void**)&yh,   g_yh);

    const int GEMM_SMEM = 3 * 2 * 128 * 72 * 2;   // 110592 B
    cudaFuncSetAttribute(gemm_fp16<0>, cudaFuncAttributeMaxDynamicSharedMemorySize, GEMM_SMEM);
    cudaFuncSetAttribute(gemm_fp16<1>, cudaFuncAttributeMaxDynamicSharedMemorySize, GEMM_SMEM);

    // 0a. convert x / in_proj_w / out_proj_w to fp16
    {
        const int total4 = (MROWS*DM + 2*DI*DM + DM*DI) / 4;
        prep_fp16<<<(total4 + 255)/256, 256>>>(
            (const float4*)x, (const float4*)in_proj_w, (const float4*)out_proj_w,
            xh, w1h, w6h);
    }
    // 0b. zero x_dbl accumulator
    zero_xdbl<<<(MROWS*XD/4)/256, 256>>>((float4*)xdbl);
    // 1. xz = x @ in_proj_w^T -> xp, z   (fp16 m16n8k16 tensor cores)
    {
        dim3 grid(2*DI/128, MROWS/128);
        gemm_fp16<1><<<grid, 256, GEMM_SMEM>>>(xh, w1h, xp, zb, MROWS, 2*DI, DM);
    }
    // 2. causal depthwise conv + bias + SiLU -> xc (4 rows/thread)
    {
        int total = (MROWS/4) * (DI/4);
        conv_silu_kernel<<<(total + 255)/256, 256>>>(xp, conv_w, conv_b, xc);
    }
    // 3. x_dbl = xc @ x_proj_w^T
    {
        dim3 grid(MROWS/64, 2);
        gemm_xdbl<<<grid, 256>>>(xc, x_proj_w, xdbl);
    }
    // 4. dt = softplus(dt_low @ dt_proj_w^T + b)
    {
        dim3 grid(DI/128, MROWS/64);
        gemm_dt<<<grid, 256>>>(xdbl, dt_proj_w, dt_proj_b, dtb);
    }
    // 5. chunked selective scan (emits y fp16)
    scan_pass1<<<(NCHAN*NCH)/32, 256>>>(xdbl, dtb, xc, A_log, Pb, Hb);
    scan_combine<<<(NCHAN*DS + 255)/256, 256>>>(Pb, Hb, Hinb);
    scan_pass2<<<(NCHAN*NCH)/32, 256>>>(xdbl, dtb, xc, zb, A_log, D_param, Hinb, yh);
    // 6. out = y @ out_proj_w^T   (fp16 tensor cores)
    {
        dim3 grid(DM/128, MROWS/128);
        gemm_fp16<0><<<grid, 256, GEMM_SMEM>>>(yh, w6h, out, nullptr, MROWS, DM, DI);
    }
}

// round 8
// speedup vs baseline: 2.1735x; 1.1742x over previous
#include <cuda_runtime.h>
#include <cuda_fp16.h>
#include <cuda_bf16.h>
#include <cstdint>

// Problem constants
static constexpr int BB = 2;
static constexpr int LSEQ = 2048;
static constexpr int DM = 768;        // d_model
static constexpr int DI = 1536;       // d_inner
static constexpr int DS = 16;         // d_state
static constexpr int RK = 48;         // dt_rank
static constexpr int XD = RK + 2*DS;  // 80
static constexpr int MROWS = BB * LSEQ;  // 4096

// Scan chunking
static constexpr int NCH = 8;
static constexpr int CHUNK = LSEQ / NCH;   // 256
static constexpr int NCHAN = BB * DI;      // 3072

// Scratch (no cudaMalloc allowed)
__device__ float g_xp  [MROWS * DI];
__device__ float g_z   [MROWS * DI];
__device__ float g_xc  [MROWS * DI];
__device__ float g_xdbl[MROWS * XD];
__device__ float g_dt  [MROWS * DI];
__device__ float g_P   [NCHAN * NCH * DS];
__device__ float g_H   [NCHAN * NCH * DS];
__device__ float g_Hin [NCHAN * NCH * DS];
// fp16 operands
__device__ __half g_xh [MROWS * DM];
__device__ __half g_w1h[2 * DI * DM];
__device__ __half g_w6h[DM * DI];
__device__ __half g_yh [MROWS * DI];

__device__ __forceinline__ float siluf(float v) {
    return v / (1.f + __expf(-v));
}
__device__ __forceinline__ float softplusf(float v) {
    if (v > 20.f) return v;
    if (v < -20.f) return __expf(v);
    return log1pf(__expf(v));
}
__device__ __forceinline__ float ex2f(float x) {
    float r;
    asm("ex2.approx.f32 %0, %1;" : "=f"(r) : "f"(x));
    return r;
}
__device__ __forceinline__ void cp16(uint32_t saddr, const void* g) {
    asm volatile("cp.async.cg.shared.global [%0], [%1], 16;" :: "r"(saddr), "l"(g));
}
#define CP_COMMIT() asm volatile("cp.async.commit_group;")
#define CP_WAIT(n)  asm volatile("cp.async.wait_group %0;" :: "n"(n))

__device__ __forceinline__ void mma_fp16(float c[4], uint32_t a0, uint32_t a1,
                                         uint32_t a2, uint32_t a3,
                                         uint32_t b0, uint32_t b1) {
    asm volatile(
        "mma.sync.aligned.m16n8k16.row.col.f32.f16.f16.f32 "
        "{%0,%1,%2,%3}, {%4,%5,%6,%7}, {%8,%9}, {%0,%1,%2,%3};"
        : "+f"(c[0]), "+f"(c[1]), "+f"(c[2]), "+f"(c[3])
        : "r"(a0), "r"(a1), "r"(a2), "r"(a3), "r"(b0), "r"(b1));
}

// ---------------------------------------------------------------------------
// fp16 tensor-core GEMM, 3-stage cp.async ring: C[M,N] = A[M,K] @ W[N,K]^T
// Block 128x128, k-tile 64 halves, 8 warps (2M x 4N), warp tile 64x32,
// mma m16n8k16 (4 k-steps per tile). Smem stride 72 halves (conflict-free).
// Dynamic smem: 3 x (128*72 A + 128*72 W) halves = 110592 B.
// EPI==0: plain store to C0 (ld = N); EPI==1: split at DI -> C0 / C1.
// Requires M%128==0, N%128==0, K%64==0.
// ---------------------------------------------------------------------------
#define ASH(b,r,k) smh[(b)*18432 + (r)*72 + (k)]
#define WSH(b,r,k) smh[(b)*18432 + 9216 + (r)*72 + (k)]

template<int EPI>
__global__ __launch_bounds__(256, 2)
void gemm_fp16(const __half* __restrict__ A, const __half* __restrict__ W,
               float* __restrict__ C0, float* __restrict__ C1,
               int M, int N, int K)
{
    extern __shared__ __half smh[];
    uint32_t sbase;
    {
        uint64_t tmp = __cvta_generic_to_shared(smh);
        sbase = (uint32_t)tmp;
    }

    const int tid  = threadIdx.x;
    const int lane = tid & 31;
    const int wid  = tid >> 5;
    const int wm   = wid & 1;          // 0..1  (M)
    const int wn   = wid >> 1;         // 0..3  (N)
    const int bm   = blockIdx.y * 128;
    const int bn   = blockIdx.x * 128;

    const int ldr = tid >> 3;          // 0..31 (row within pass)
    const int ldc = (tid & 7) * 8;     // half-col (8 halves = 16B)
    const int g   = lane >> 2;
    const int q4  = lane & 3;

    float c[4][4][4];
#pragma unroll
    for (int i = 0; i < 4; ++i)
#pragma unroll
        for (int j = 0; j < 4; ++j)
#pragma unroll
            for (int q = 0; q < 4; ++q) c[i][j][q] = 0.f;

    const __half* Abase = A + (size_t)bm * K + ldc;
    const __half* Wbase = W + (size_t)bn * K + ldc;

#define ISSUE(k0, buf) {                                                     \
    _Pragma("unroll") for (int p = 0; p < 4; ++p) {                          \
        int r = ldr + p*32;                                                  \
        cp16(sbase + (uint32_t)(((buf)*18432 + r*72 + ldc))*2,               \
             Abase + (size_t)r * K + (k0));                                  \
        cp16(sbase + (uint32_t)(((buf)*18432 + 9216 + r*72 + ldc))*2,        \
             Wbase + (size_t)r * K + (k0)); } }

#define COMPUTE(buf, ks) {                                                   \
    const int kk = (ks)*16 + 2*q4;                                           \
    uint32_t a[4][4], b[4][2];                                               \
    _Pragma("unroll") for (int mt = 0; mt < 4; ++mt) {                       \
        int r = wm*64 + mt*16 + g;                                           \
        a[mt][0] = *(const uint32_t*)&ASH(buf, r,   kk);                     \
        a[mt][1] = *(const uint32_t*)&ASH(buf, r+8, kk);                     \
        a[mt][2] = *(const uint32_t*)&ASH(buf, r,   kk+8);                   \
        a[mt][3] = *(const uint32_t*)&ASH(buf, r+8, kk+8); }                 \
    _Pragma("unroll") for (int nt = 0; nt < 4; ++nt) {                       \
        int n = wn*32 + nt*8 + g;                                            \
        b[nt][0] = *(const uint32_t*)&WSH(buf, n, kk);                       \
        b[nt][1] = *(const uint32_t*)&WSH(buf, n, kk+8); }                   \
    _Pragma("unroll") for (int mt = 0; mt < 4; ++mt)                         \
        _Pragma("unroll") for (int nt = 0; nt < 4; ++nt)                     \
            mma_fp16(c[mt][nt], a[mt][0], a[mt][1], a[mt][2], a[mt][3],     \
                     b[nt][0], b[nt][1]); }

    ISSUE(0, 0);
    CP_COMMIT();
    ISSUE(64, 1);
    CP_COMMIT();

    const int NT = K / 64;
    for (int t = 0; t < NT; ++t) {
        const int buf = t % 3;
        CP_WAIT(1);                 // group t complete (in-order retirement)
        __syncthreads();            // all warps done with buffer (t+2)%3
        if (t + 2 < NT) {
            ISSUE((t+2)*64, (t+2)%3);
        }
        CP_COMMIT();                // unconditional: keeps group accounting aligned
        COMPUTE(buf, 0);
        COMPUTE(buf, 1);
        COMPUTE(buf, 2);
        COMPUTE(buf, 3);
    }

    // epilogue
    const int q2 = (lane & 3) * 2;
    float* base;
    int ncol0, ldo;
    if (EPI == 0) { base = C0; ncol0 = bn; ldo = N; }
    else {
        base = (bn < DI) ? C0 : C1;
        ncol0 = (bn < DI) ? bn : (bn - DI);
        ldo = DI;
    }
#pragma unroll
    for (int mt = 0; mt < 4; ++mt) {
#pragma unroll
        for (int nt = 0; nt < 4; ++nt) {
            int row = bm + wm*64 + mt*16 + g;
            int col = ncol0 + wn*32 + nt*8 + q2;
            float2 v0 = make_float2(c[mt][nt][0], c[mt][nt][1]);
            float2 v1 = make_float2(c[mt][nt][2], c[mt][nt][3]);
            *(float2*)(base + (size_t)row * ldo + col) = v0;
            *(float2*)(base + (size_t)(row + 8) * ldo + col) = v1;
        }
    }
#undef ISSUE
#undef COMPUTE
}

// ---------------------------------------------------------------------------
// Convert x, in_proj_w, out_proj_w to fp16
// ---------------------------------------------------------------------------
__global__ __launch_bounds__(256)
void prep_fp16(const float4* __restrict__ x, const float4* __restrict__ w1,
               const float4* __restrict__ w6,
               __half* __restrict__ xh, __half* __restrict__ w1h,
               __half* __restrict__ w6h)
{
    const int N1 = MROWS*DM/4, N2 = 2*DI*DM/4, N3 = DM*DI/4;
    int i = blockIdx.x * 256 + threadIdx.x;
    float4 v; __half* o; int off;
    if (i < N1)            { v = x[i];        o = xh;  off = i*4; }
    else if (i < N1+N2)    { v = w1[i-N1];    o = w1h; off = (i-N1)*4; }
    else if (i < N1+N2+N3) { v = w6[i-N1-N2]; o = w6h; off = (i-N1-N2)*4; }
    else return;
    __half2* o2 = (__half2*)(o + off);
    o2[0] = __floats2half2_rn(v.x, v.y);
    o2[1] = __floats2half2_rn(v.z, v.w);
}

// ---------------------------------------------------------------------------
// Depthwise causal conv1d (K=4, left-pad 3) + bias + SiLU
// Each thread: 4 consecutive l positions x 4 channels (float4).
// ---------------------------------------------------------------------------
__global__ __launch_bounds__(256)
void conv_silu_kernel(const float* __restrict__ xp, const float* __restrict__ cw,
                      const float* __restrict__ cb, float* __restrict__ xc)
{
    const int NDQ = DI / 4;
    int idx = blockIdx.x * blockDim.x + threadIdx.x;
    if (idx >= (MROWS/4) * NDQ) return;
    int dq = idx % NDQ;
    int rg = idx / NDQ;
    int b  = rg / (LSEQ/4);
    int l0 = (rg % (LSEQ/4)) * 4;
    int d  = dq * 4;

    float4 wq0 = *(const float4*)(cw + d*4 + 0);
    float4 wq1 = *(const float4*)(cw + d*4 + 4);
    float4 wq2 = *(const float4*)(cw + d*4 + 8);
    float4 wq3 = *(const float4*)(cw + d*4 + 12);
    float4 bias = *(const float4*)(cb + d);

    const float* base = xp + ((size_t)(b * LSEQ + l0)) * DI + d;

    float4 in[7];
#pragma unroll
    for (int j = 0; j < 7; ++j) {
        int l = l0 - 3 + j;
        if (l >= 0) in[j] = *(const float4*)(base + (size_t)(j - 3) * DI);
        else        in[j] = make_float4(0.f, 0.f, 0.f, 0.f);
    }

    float* outp = xc + ((size_t)(b * LSEQ + l0)) * DI + d;
#pragma unroll
    for (int i = 0; i < 4; ++i) {
        float4 acc = bias;
        acc.x = fmaf(in[i+0].x, wq0.x, acc.x); acc.y = fmaf(in[i+0].y, wq1.x, acc.y);
        acc.z = fmaf(in[i+0].z, wq2.x, acc.z); acc.w = fmaf(in[i+0].w, wq3.x, acc.w);
        acc.x = fmaf(in[i+1].x, wq0.y, acc.x); acc.y = fmaf(in[i+1].y, wq1.y, acc.y);
        acc.z = fmaf(in[i+1].z, wq2.y, acc.z); acc.w = fmaf(in[i+1].w, wq3.y, acc.w);
        acc.x = fmaf(in[i+2].x, wq0.z, acc.x); acc.y = fmaf(in[i+2].y, wq1.z, acc.y);
        acc.z = fmaf(in[i+2].z, wq2.z, acc.z); acc.w = fmaf(in[i+2].w, wq3.z, acc.w);
        acc.x = fmaf(in[i+3].x, wq0.w, acc.x); acc.y = fmaf(in[i+3].y, wq1.w, acc.y);
        acc.z = fmaf(in[i+3].z, wq2.w, acc.z); acc.w = fmaf(in[i+3].w, wq3.w, acc.w);
        float4 r = make_float4(siluf(acc.x), siluf(acc.y), siluf(acc.z), siluf(acc.w));
        *(float4*)(outp + (size_t)i * DI) = r;
    }
}

// ---------------------------------------------------------------------------
__global__ __launch_bounds__(256)
void zero_xdbl(float4* __restrict__ x)
{
    int i = blockIdx.x * 256 + threadIdx.x;
    x[i] = make_float4(0.f, 0.f, 0.f, 0.f);
}

// ---------------------------------------------------------------------------
// x_dbl = xc @ x_proj_w^T   [4096,1536] x [80,1536]^T -> [4096,80]
// BM=64, 4x5 micro-tile, double-buffered, 4-way K split, atomicAdd epilogue.
// grid = (64, 4) = 256 blocks.
// ---------------------------------------------------------------------------
__global__ __launch_bounds__(256)
void gemm_xdbl(const float* __restrict__ A, const float* __restrict__ W,
               float* __restrict__ C)
{
    __shared__ float As[2][32][68];
    __shared__ float Ws[2][32][81];
    const int tid = threadIdx.x;
    const int bm = blockIdx.x * 64;
    const int kbeg = blockIdx.y * (DI/4);
    const int tr = tid >> 4;
    const int tc = tid & 15;
    const int cc = tid & 31;
    const int r0 = tid >> 5;

    float acc[4][5];
#pragma unroll
    for (int i = 0; i < 4; ++i)
#pragma unroll
        for (int j = 0; j < 5; ++j) acc[i][j] = 0.f;

    float a_st[8], w_st[10];

#define XLOAD(k0) {                                                          \
    _Pragma("unroll") for (int p = 0; p < 8; ++p)                            \
        a_st[p] = A[(size_t)(bm + r0 + p*8) * DI + (k0) + cc];               \
    _Pragma("unroll") for (int p = 0; p < 10; ++p)                           \
        w_st[p] = W[(size_t)(r0 + p*8) * DI + (k0) + cc]; }
#define XSTORE(buf) {                                                        \
    _Pragma("unroll") for (int p = 0; p < 8; ++p)                            \
        As[buf][cc][r0 + p*8] = a_st[p];                                     \
    _Pragma("unroll") for (int p = 0; p < 10; ++p)                           \
        Ws[buf][cc][r0 + p*8] = w_st[p]; }

    XLOAD(kbeg);
    XSTORE(0);
    __syncthreads();

    const int NT = (DI/4) / 32;   // 12
    for (int t = 0; t < NT; ++t) {
        const int cur = t & 1;
        if (t + 1 < NT) XLOAD(kbeg + (t+1)*32);
#pragma unroll
        for (int k = 0; k < 32; ++k) {
            float4 a4 = *(const float4*)&As[cur][k][tr*4];
            float a[4] = {a4.x, a4.y, a4.z, a4.w};
#pragma unroll
            for (int j = 0; j < 5; ++j) {
                float w = Ws[cur][k][tc*5 + j];
#pragma unroll
                for (int i = 0; i < 4; ++i)
                    acc[i][j] = fmaf(a[i], w, acc[i][j]);
            }
        }
        if (t + 1 < NT) {
            XSTORE(cur^1);
            __syncthreads();
        }
    }
#pragma unroll
    for (int i = 0; i < 4; ++i)
#pragma unroll
        for (int j = 0; j < 5; ++j)
            atomicAdd(&C[(size_t)(bm + tr*4 + i) * XD + tc*5 + j], acc[i][j]);
#undef XLOAD
#undef XSTORE
}

// ---------------------------------------------------------------------------
// dt = softplus( x_dbl[:, :48] @ dt_proj_w^T + b )  -> [4096,1536]
// ---------------------------------------------------------------------------
__global__ __launch_bounds__(256)
void gemm_dt(const float* __restrict__ xdbl, const float* __restrict__ Wt,
             const float* __restrict__ bt, float* __restrict__ dt)
{
    __shared__ float s_inT[48][68];
    __shared__ float s_w[48][132];
    const int tid = threadIdx.x;
    const int m0 = blockIdx.y * 64;
    const int n0 = blockIdx.x * 128;

    for (int i = tid; i < 64*48; i += 256) {
        int r = i / 48, q = i % 48;
        s_inT[q][r] = xdbl[(size_t)(m0 + r) * XD + q];
    }
    for (int i = tid; i < 128*48; i += 256) {
        int col = i / 48, q = i % 48;
        s_w[q][col] = Wt[(size_t)(n0 + col) * RK + q];
    }
    __syncthreads();

    const int col = (tid & 31) * 4;
    const int row0 = (tid >> 5) * 8;

    float acc[8][4];
    {
        float4 b4 = *(const float4*)(bt + n0 + col);
#pragma unroll
        for (int r = 0; r < 8; ++r) {
            acc[r][0] = b4.x; acc[r][1] = b4.y; acc[r][2] = b4.z; acc[r][3] = b4.w;
        }
    }
#pragma unroll
    for (int q = 0; q < 48; ++q) {
        float4 a0 = *(const float4*)&s_inT[q][row0];
        float4 a1 = *(const float4*)&s_inT[q][row0 + 4];
        float4 w4 = *(const float4*)&s_w[q][col];
        float a[8] = {a0.x,a0.y,a0.z,a0.w,a1.x,a1.y,a1.z,a1.w};
#pragma unroll
        for (int r = 0; r < 8; ++r) {
            acc[r][0] = fmaf(a[r], w4.x, acc[r][0]);
            acc[r][1] = fmaf(a[r], w4.y, acc[r][1]);
            acc[r][2] = fmaf(a[r], w4.z, acc[r][2]);
            acc[r][3] = fmaf(a[r], w4.w, acc[r][3]);
        }
    }
#pragma unroll
    for (int r = 0; r < 8; ++r) {
        float* p = dt + (size_t)(m0 + row0 + r) * DI + n0 + col;
        float4 v = make_float4(softplusf(acc[r][0]), softplusf(acc[r][1]),
                               softplusf(acc[r][2]), softplusf(acc[r][3]));
        *(float4*)p = v;
    }
}

// ---------------------------------------------------------------------------
// Chunked selective scan, pass 1. 8 lanes/unit, 2 states/lane.
// UNIT ORDER: unit = c * NCHAN + ch  -> the 4 units of a warp are 4
// consecutive channels at the SAME chunk => dt/xc loads coalesce (16B),
// B loads broadcast (same (b,l) for the whole warp).
// ---------------------------------------------------------------------------
__global__ __launch_bounds__(256)
void scan_pass1(const float* __restrict__ xdbl, const float* __restrict__ dt,
                const float* __restrict__ xc, const float* __restrict__ A_log,
                float* __restrict__ P, float* __restrict__ H)
{
    const float LOG2E = 1.4426950408889634f;
    const int s = threadIdx.x & 7;
    const int unit = blockIdx.x * 32 + (threadIdx.x >> 3);
    const int c  = unit / NCHAN;       // chunk
    const int ch = unit % NCHAN;       // channel
    const int b = ch / DI;
    const int d = ch % DI;

    float2 Alog2 = *(const float2*)(A_log + d*DS + 2*s);
    const float A0 = -__expf(Alog2.x) * LOG2E;
    const float A1 = -__expf(Alog2.y) * LOG2E;
    float h0 = 0.f, h1 = 0.f, P0 = 1.f, P1 = 1.f;

    const int row0 = b * LSEQ + c * CHUNK;
    const float* dt_p = dt + (size_t)row0 * DI + d;
    const float* xc_p = xc + (size_t)row0 * DI + d;
    const float* xd_p = xdbl + (size_t)row0 * XD;

#pragma unroll 4
    for (int l = 0; l < CHUNK; ++l) {
        float dtv = __ldg(dt_p);
        float xcv = __ldg(xc_p);
        float2 Bv = *(const float2*)(xd_p + RK + 2*s);
        float a0 = ex2f(dtv * A0);
        float a1 = ex2f(dtv * A1);
        float bx = dtv * xcv;
        P0 *= a0; P1 *= a1;
        h0 = fmaf(a0, h0, bx * Bv.x);
        h1 = fmaf(a1, h1, bx * Bv.y);
        dt_p += DI; xc_p += DI; xd_p += XD;
    }
    *(float2*)(P + unit * DS + 2*s) = make_float2(P0, P1);
    *(float2*)(H + unit * DS + 2*s) = make_float2(h0, h1);
}

// ---------------------------------------------------------------------------
// Combine: serial scan over the 8 chunk transitions per (channel, state).
// P/H/Hin indexed by unit = c*NCHAN + ch.
// ---------------------------------------------------------------------------
__global__ __launch_bounds__(256)
void scan_combine(const float* __restrict__ P, const float* __restrict__ H,
                  float* __restrict__ Hin)
{
    int idx = blockIdx.x * blockDim.x + threadIdx.x;
    if (idx >= NCHAN * DS) return;
    int ch = idx >> 4;
    int s = idx & 15;
    float run = 0.f;
#pragma unroll
    for (int c = 0; c < NCH; ++c) {
        int o = (c * NCHAN + ch) * DS + s;
        Hin[o] = run;
        run = fmaf(P[o], run, H[o]);
    }
}

// ---------------------------------------------------------------------------
// Pass 2: y = (sum_s h*C + xc*D) * silu(z), emitted fp16. Same unit order.
// ---------------------------------------------------------------------------
__global__ __launch_bounds__(256)
void scan_pass2(const float* __restrict__ xdbl, const float* __restrict__ dt,
                const float* __restrict__ xc, const float* __restrict__ z,
                const float* __restrict__ A_log, const float* __restrict__ Dp,
                const float* __restrict__ Hin, __half* __restrict__ y)
{
    const float LOG2E = 1.4426950408889634f;
    const int s = threadIdx.x & 7;
    const int unit = blockIdx.x * 32 + (threadIdx.x >> 3);
    const int c  = unit / NCHAN;
    const int ch = unit % NCHAN;
    const int b = ch / DI;
    const int d = ch % DI;

    float2 Alog2 = *(const float2*)(A_log + d*DS + 2*s);
    const float A0 = -__expf(Alog2.x) * LOG2E;
    const float A1 = -__expf(Alog2.y) * LOG2E;
    const float Dv = Dp[d];
    float2 h2 = *(const float2*)(Hin + unit * DS + 2*s);
    float h0 = h2.x, h1 = h2.y;

    const int row0 = b * LSEQ + c * CHUNK;
    const float* dt_p = dt + (size_t)row0 * DI + d;
    const float* xc_p = xc + (size_t)row0 * DI + d;
    const float* z_p  = z  + (size_t)row0 * DI + d;
    const float* xd_p = xdbl + (size_t)row0 * XD;
    __half* y_p = y + (size_t)row0 * DI + d;

#pragma unroll 4
    for (int l = 0; l < CHUNK; ++l) {
        float dtv = __ldg(dt_p);
        float xcv = __ldg(xc_p);
        float2 Bv = *(const float2*)(xd_p + RK + 2*s);
        float2 Cv = *(const float2*)(xd_p + RK + DS + 2*s);

        float a0 = ex2f(dtv * A0);
        float a1 = ex2f(dtv * A1);
        float bx = dtv * xcv;
        h0 = fmaf(a0, h0, bx * Bv.x);
        h1 = fmaf(a1, h1, bx * Bv.y);
        float p = fmaf(h0, Cv.x, h1 * Cv.y);
        p += __shfl_xor_sync(0xffffffffu, p, 1);
        p += __shfl_xor_sync(0xffffffffu, p, 2);
        p += __shfl_xor_sync(0xffffffffu, p, 4);
        if (s == 0) {
            float zv = __ldg(z_p);
            float val = (p + xcv * Dv) * siluf(zv);
            *y_p = __float2half_rn(val);
        }
        dt_p += DI; xc_p += DI; z_p += DI; y_p += DI; xd_p += XD;
    }
}

// ---------------------------------------------------------------------------
extern "C" void kernel_launch(void* const* d_in, const int* in_sizes, int n_in,
                              void* d_out, int out_size)
{
    const float* x          = (const float*)d_in[0];
    const float* in_proj_w  = (const float*)d_in[1];
    const float* conv_w     = (const float*)d_in[2];
    const float* conv_b     = (const float*)d_in[3];
    const float* A_log      = (const float*)d_in[4];
    const float* D_param    = (const float*)d_in[5];
    const float* x_proj_w   = (const float*)d_in[6];
    const float* dt_proj_w  = (const float*)d_in[7];
    const float* dt_proj_b  = (const float*)d_in[8];
    const float* out_proj_w = (const float*)d_in[9];
    float* out = (float*)d_out;

    float *xp, *zb, *xc, *xdbl, *dtb, *Pb, *Hb, *Hinb;
    __half *xh, *w1h, *w6h, *yh;
    cudaGetSymbolAddress((void**)&xp,   g_xp);
    cudaGetSymbolAddress((void**)&zb,   g_z);
    cudaGetSymbolAddress((void**)&xc,   g_xc);
    cudaGetSymbolAddress((void**)&xdbl, g_xdbl);
    cudaGetSymbolAddress((void**)&dtb,  g_dt);
    cudaGetSymbolAddress((void**)&Pb,   g_P);
    cudaGetSymbolAddress((void**)&Hb,   g_H);
    cudaGetSymbolAddress((void**)&Hinb, g_Hin);
    cudaGetSymbolAddress((void**)&xh,   g_xh);
    cudaGetSymbolAddress((void**)&w1h,  g_w1h);
    cudaGetSymbolAddress((void**)&w6h,  g_w6h);
    cudaGetSymbolAddress((void**)&yh,   g_yh);

    const int GEMM_SMEM = 3 * 2 * 128 * 72 * 2;   // 110592 B
    cudaFuncSetAttribute(gemm_fp16<0>, cudaFuncAttributeMaxDynamicSharedMemorySize, GEMM_SMEM);
    cudaFuncSetAttribute(gemm_fp16<1>, cudaFuncAttributeMaxDynamicSharedMemorySize, GEMM_SMEM);

    // 0a. convert x / in_proj_w / out_proj_w to fp16
    {
        const int total4 = (MROWS*DM + 2*DI*DM + DM*DI) / 4;
        prep_fp16<<<(total4 + 255)/256, 256>>>(
            (const float4*)x, (const float4*)in_proj_w, (const float4*)out_proj_w,
            xh, w1h, w6h);
    }
    // 0b. zero x_dbl accumulator
    zero_xdbl<<<(MROWS*XD/4)/256, 256>>>((float4*)xdbl);
    // 1. xz = x @ in_proj_w^T -> xp, z   (fp16 tensor cores)
    {
        dim3 grid(2*DI/128, MROWS/128);
        gemm_fp16<1><<<grid, 256, GEMM_SMEM>>>(xh, w1h, xp, zb, MROWS, 2*DI, DM);
    }
    // 2. causal depthwise conv + bias + SiLU -> xc
    {
        int total = (MROWS/4) * (DI/4);
        conv_silu_kernel<<<(total + 255)/256, 256>>>(xp, conv_w, conv_b, xc);
    }
    // 3. x_dbl = xc @ x_proj_w^T  (4-way K split)
    {
        dim3 grid(MROWS/64, 4);
        gemm_xdbl<<<grid, 256>>>(xc, x_proj_w, xdbl);
    }
    // 4. dt = softplus(dt_low @ dt_proj_w^T + b)
    {
        dim3 grid(DI/128, MROWS/64);
        gemm_dt<<<grid, 256>>>(xdbl, dt_proj_w, dt_proj_b, dtb);
    }
    // 5. chunked selective scan (channel-major unit order)
    scan_pass1<<<(NCHAN*NCH)/32, 256>>>(xdbl, dtb, xc, A_log, Pb, Hb);
    scan_combine<<<(NCHAN*DS + 255)/256, 256>>>(Pb, Hb, Hinb);
    scan_pass2<<<(NCHAN*NCH)/32, 256>>>(xdbl, dtb, xc, zb, A_log, D_param, Hinb, yh);
    // 6. out = y @ out_proj_w^T   (fp16 tensor cores)
    {
        dim3 grid(DM/128, MROWS/128);
        gemm_fp16<0><<<grid, 256, GEMM_SMEM>>>(yh, w6h, out, nullptr, MROWS, DM, DI);
    }
}